// round 11
// baseline (speedup 1.0000x reference)
#include <cuda_runtime.h>
#include <math.h>
#include <stdint.h>

#define XP    16386
#define XS    16640          // row stride (65*256)
#define NXV   16384
#define KPAD  16416          // forward-DFT K extent (18*912)
#define NB    16

// ------------------- static device buffers -------------------
__device__ float d_h   [(size_t)NB * 64 * XS];
__device__ float d_g   [(size_t)NB * 64 * XS];
__device__ float d_gmid[(size_t)NB * 128 * XS];
__device__ float d_ftab[(size_t)KPAD * 128];      // [x][2m]=cos, [2m+1]=-sin
__device__ float d_itab[(size_t)128 * XS];        // [2m][x]=cos, [2m+1][x]=sin
__device__ float d_part[(size_t)18 * 2048 * 128];
__device__ float d_fw  [2048 * 128];
__device__ float d_outm[1024 * 128];
__device__ float d_coefW[64 * 64];                // aw * W for current block
__device__ float d_w1T [4 * 64 * 128];
__device__ float d_w2T [4 * 128 * 64];
__device__ float d_fc1T[64 * 128];

// ------------------- f32x2 packed helpers -------------------
__device__ __forceinline__ uint64_t pack2(float lo, float hi) {
    uint64_t r;
    asm("mov.b64 %0, {%1, %2};" : "=l"(r) : "f"(lo), "f"(hi));
    return r;
}
__device__ __forceinline__ void unpack2(uint64_t v, float& lo, float& hi) {
    asm("mov.b64 {%0, %1}, %2;" : "=f"(lo), "=f"(hi) : "l"(v));
}
#define FMA2(d, a, b) \
    asm("fma.rn.f32x2 %0, %1, %2, %0;" : "+l"(d) : "l"(a), "l"(b))

__device__ __forceinline__ uint32_t s2u(const void* p) {
    return (uint32_t)__cvta_generic_to_shared(p);
}
__device__ __forceinline__ void cp16(uint32_t s, const float* g) {
    asm volatile("cp.async.cg.shared.global [%0], [%1], 16;"
                 :: "r"(s), "l"(__cvta_generic_to_global(g)));
}
#define CP_COMMIT asm volatile("cp.async.commit_group;")
#define CP_WAIT(n) asm volatile("cp.async.wait_group %0;" :: "n"(n))

__device__ __forceinline__ float softplus_(float x) {
    return (x > 20.f) ? x : log1pf(expf(x));
}
__device__ __forceinline__ float gelu_(float v) {
    return 0.5f * v * (1.0f + erff(v * 0.70710678118654752f));
}

// ------------------- mega setup kernel -------------------
__global__ void __launch_bounds__(256) setup_kernel(
    const float* __restrict__ xin, const float* __restrict__ gin,
    const float* __restrict__ fc0_w, const float* __restrict__ fc0_b,
    const float* __restrict__ g_w1, const float* __restrict__ g_w2,
    const float* __restrict__ fc1_w)
{
    const int blk = blockIdx.x;
    const int tid = threadIdx.x;
    if (blk < 1024) {                             // ---- fc0 ----
        __shared__ float sw[64 * 32];
        __shared__ float sb[64];
        for (int l = tid; l < 64 * 31; l += 256) {
            int wo = l / 31, c = l - wo * 31;
            sw[wo * 32 + c] = fc0_w[l];
        }
        if (tid < 64) sb[tid] = fc0_b[tid];
        __syncthreads();
        int b = blk >> 6;
        int x = ((blk & 63) << 8) + tid;
        float rin[31];
        const float* xi = xin + ((size_t)b * NXV + x) * 30;
#pragma unroll
        for (int c = 0; c < 30; c++) rin[c] = __ldg(&xi[c]);
        rin[30] = __ldg(&gin[(size_t)b * NXV + x]);
        for (int wo = 0; wo < 64; wo++) {
            float acc = sb[wo];
#pragma unroll
            for (int c = 0; c < 31; c++) acc = fmaf(rin[c], sw[wo * 32 + c], acc);
            d_h[(size_t)(b * 64 + wo) * XS + x] = acc;
        }
    } else if (blk < 2048) {                      // ---- zero h tail ----
        int idx = (blk - 1024) * 256 + tid;
        int row = idx >> 8, col = NXV + (idx & 255);
        d_h[(size_t)row * XS + col] = 0.f;
    } else if (blk < 2336) {                      // ---- weight transposes ----
        int idx = (blk - 2048) * 256 + tid;
        if (idx < 32768) {
            int i = idx >> 13, r = idx & 8191, c = r >> 7, j = r & 127;
            d_w1T[idx] = g_w1[(i * 128 + j) * 64 + c];
        } else if (idx < 65536) {
            int t = idx - 32768;
            int i = t >> 13, r = t & 8191, j = r >> 6, o = r & 63;
            d_w2T[t] = g_w2[(i * 64 + o) * 128 + j];
        } else if (idx < 73728) {
            int t = idx - 65536;
            int c = t >> 7, j = t & 127;
            d_fc1T[t] = fc1_w[j * 64 + c];
        }
    } else if (blk < 10544) {                     // ---- ftab ----
        int idx = (blk - 2336) * 256 + tid;
        int x = idx >> 7, t = idx & 127, m = t >> 1;
        float v = 0.f;
        if (x < XP) {
            int u = (x * m) % XP;
            float s, c;
            sincospif(2.0f * (float)u / (float)XP, &s, &c);
            v = (t & 1) ? -s : c;
        }
        d_ftab[idx] = v;
    } else {                                      // ---- itab ----
        int idx = (blk - 10544) * 256 + tid;
        int t = idx / XS, x = idx - t * XS, m = t >> 1;
        float v = 0.f;
        if (x < XP) {
            int u = (x * m) % XP;
            float s, c;
            sincospif(2.0f * (float)u / (float)XP, &s, &c);
            v = (t & 1) ? s : c;
        }
        d_itab[idx] = v;
    }
}

__global__ void coefw_kernel(const float* __restrict__ w_w,
                             const float* __restrict__ alpha_w, int blk) {
    int i = blockIdx.x * 256 + threadIdx.x;      // 4096
    d_coefW[i] = softplus_(__ldg(alpha_w)) * __ldg(&w_w[blk * 4096 + i]);
}

// ------------------- 1x1 conv (cp.async double-buffered, f32x2) -------------------
template<int CIN, int COUT, int ACT>
__global__ void __launch_bounds__(256, 2) conv1x1_kernel(
    const float* __restrict__ in,
    const float* __restrict__ wT,
    const float* __restrict__ bias,
    float* __restrict__ out,
    const float* __restrict__ alpha)
{
    constexpr int BP  = (COUT >= 128) ? 128 : 256;
    constexpr int TPp = BP / 32;
    constexpr int TOc = COUT / 8;
    constexpr int OP  = TOc / 2;
    constexpr int NTt = CIN / 16;
    constexpr int SIC = (16 * BP / 4) / 256;
    constexpr int SWC = (16 * COUT / 4) / 256;
    __shared__ float si [2][16][BP];
    __shared__ float swt[2][16][COUT];
    const int b   = blockIdx.y;
    const int p0  = blockIdx.x * BP;
    const int tid = threadIdx.x;
    const int po  = (tid & 31) * TPp;
    const int oo  = (tid >> 5) * TOc;

    const float* inb = in + (size_t)b * CIN * XS + p0;

    uint64_t acc[TPp][OP];
#pragma unroll
    for (int p = 0; p < TPp; p++)
#pragma unroll
        for (int j = 0; j < OP; j++) acc[p][j] = 0ull;

    {
#pragma unroll
        for (int l = 0; l < SIC; l++) {
            int c = l * 256 + tid;
            int k = c / (BP / 4), q = (c % (BP / 4)) * 4;
            cp16(s2u(&si[0][k][q]), inb + k * XS + q);
        }
#pragma unroll
        for (int l = 0; l < SWC; l++) {
            int c = l * 256 + tid;
            int k = c / (COUT / 4), q = (c % (COUT / 4)) * 4;
            cp16(s2u(&swt[0][k][q]), wT + k * COUT + q);
        }
        CP_COMMIT;
    }
#pragma unroll
    for (int t = 0; t < NTt; t++) {
        const int buf = t & 1;
        if (t + 1 < NTt) {
            const int c0 = (t + 1) * 16;
#pragma unroll
            for (int l = 0; l < SIC; l++) {
                int c = l * 256 + tid;
                int k = c / (BP / 4), q = (c % (BP / 4)) * 4;
                cp16(s2u(&si[buf ^ 1][k][q]), inb + (c0 + k) * XS + q);
            }
#pragma unroll
            for (int l = 0; l < SWC; l++) {
                int c = l * 256 + tid;
                int k = c / (COUT / 4), q = (c % (COUT / 4)) * 4;
                cp16(s2u(&swt[buf ^ 1][k][q]), wT + (c0 + k) * COUT + q);
            }
            CP_COMMIT;
            CP_WAIT(1);
        } else {
            CP_WAIT(0);
        }
        __syncthreads();
#pragma unroll
        for (int k = 0; k < 16; k++) {
            uint64_t pa[TPp];
#pragma unroll
            for (int u = 0; u < TPp / 4; u++) {
                float4 av = *(const float4*)&si[buf][k][po + 4 * u];
                pa[4*u+0] = pack2(av.x, av.x);
                pa[4*u+1] = pack2(av.y, av.y);
                pa[4*u+2] = pack2(av.z, av.z);
                pa[4*u+3] = pack2(av.w, av.w);
            }
#pragma unroll
            for (int j = 0; j < OP; j++) {
                uint64_t wv = *(const uint64_t*)&swt[buf][k][oo + 2 * j];
#pragma unroll
                for (int p = 0; p < TPp; p++) FMA2(acc[p][j], wv, pa[p]);
            }
        }
        __syncthreads();
    }

    float scv = 1.f;
    if (ACT == 2) scv = softplus_(__ldg(alpha));
#pragma unroll
    for (int j = 0; j < OP; j++) {
        int o0 = oo + 2 * j;
        float b0 = __ldg(&bias[o0]);
        float b1 = __ldg(&bias[o0 + 1]);
        float vlo[TPp], vhi[TPp];
#pragma unroll
        for (int p = 0; p < TPp; p++) {
            unpack2(acc[p][j], vlo[p], vhi[p]);
            vlo[p] += b0; vhi[p] += b1;
            if (ACT == 1) { vlo[p] = gelu_(vlo[p]); vhi[p] = gelu_(vhi[p]); }
            if (ACT == 2) { vlo[p] *= scv; vhi[p] *= scv; }
        }
        float* r0 = out + ((size_t)b * COUT + o0) * XS + p0 + po;
        float* r1 = r0 + XS;
#pragma unroll
        for (int q = 0; q < TPp / 4; q++) {
            *(float4*)&r0[4*q] = make_float4(vlo[4*q], vlo[4*q+1], vlo[4*q+2], vlo[4*q+3]);
            *(float4*)&r1[4*q] = make_float4(vhi[4*q], vhi[4*q+1], vhi[4*q+2], vhi[4*q+3]);
        }
    }
}

// -------- forward DFT: 512 threads, 4 rows x 8 comps per thread --------
__global__ void __launch_bounds__(512, 2) fdft_kernel() {
    const int rt = blockIdx.x;     // 0..15 : 128-row tiles (8 h, 8 g)
    const int ks = blockIdx.y;     // 0..17 : K splits of 912 (57 tiles)
    const float* src = (rt < 8) ? d_h + (size_t)rt * 128 * XS
                                : d_g + (size_t)(rt - 8) * 128 * XS;
    const int kbase = ks * 912;

    __shared__ float sa[2][16][260];   // rows DUPLICATED: [k][2*row]
    __shared__ float sf[2][16][128];   // ftab straight [k][comp] (cp.async)
    const int tid = threadIdx.x;
    const int cg = tid & 15;           // comps cg*4, 64+cg*4
    const int rg = tid >> 4;           // rows rg*4..+3  (0..31)

    uint64_t acc[4][4];
#pragma unroll
    for (int r = 0; r < 4; r++)
#pragma unroll
        for (int j = 0; j < 4; j++) acc[r][j] = 0ull;

    float ra[4];
    // prefetch tile 0
    {
        int c = tid;   // 512 chunks cover 16x128 floats
        cp16(s2u(&sf[0][c >> 5][(c & 31) * 4]),
             &d_ftab[(size_t)(kbase + (c >> 5)) * 128 + (c & 31) * 4]);
    }
    CP_COMMIT;
#pragma unroll
    for (int l = 0; l < 4; l++) {
        int c = l * 512 + tid;
        ra[l] = src[(size_t)(c >> 4) * XS + kbase + (c & 15)];
    }
#pragma unroll
    for (int l = 0; l < 4; l++) {
        int c = l * 512 + tid;
        *(uint64_t*)&sa[0][c & 15][2 * (c >> 4)] = pack2(ra[l], ra[l]);
    }
    CP_WAIT(0);
    __syncthreads();

    for (int t = 0; t < 57; t++) {
        const int buf = t & 1;
        if (t < 56) {
            const int kb = kbase + (t + 1) * 16;
            {
                int c = tid;
                cp16(s2u(&sf[buf ^ 1][c >> 5][(c & 31) * 4]),
                     &d_ftab[(size_t)(kb + (c >> 5)) * 128 + (c & 31) * 4]);
            }
            CP_COMMIT;
#pragma unroll
            for (int l = 0; l < 4; l++) {
                int c = l * 512 + tid;
                ra[l] = src[(size_t)(c >> 4) * XS + kb + (c & 15)];
            }
        }
#pragma unroll
        for (int k = 0; k < 16; k++) {
            ulonglong2 c0 = *(const ulonglong2*)&sf[buf][k][cg * 4];
            ulonglong2 c1 = *(const ulonglong2*)&sf[buf][k][64 + cg * 4];
            ulonglong2 r01 = *(const ulonglong2*)&sa[buf][k][rg * 8];
            ulonglong2 r23 = *(const ulonglong2*)&sa[buf][k][rg * 8 + 4];
            uint64_t rd[4] = {r01.x, r01.y, r23.x, r23.y};
#pragma unroll
            for (int r = 0; r < 4; r++) {
                FMA2(acc[r][0], rd[r], c0.x);
                FMA2(acc[r][1], rd[r], c0.y);
                FMA2(acc[r][2], rd[r], c1.x);
                FMA2(acc[r][3], rd[r], c1.y);
            }
        }
        if (t < 56) {
#pragma unroll
            for (int l = 0; l < 4; l++) {
                int c = l * 512 + tid;
                *(uint64_t*)&sa[buf ^ 1][c & 15][2 * (c >> 4)] = pack2(ra[l], ra[l]);
            }
            CP_WAIT(0);
        }
        __syncthreads();
    }
#pragma unroll
    for (int r = 0; r < 4; r++) {
        int row = rt * 128 + rg * 4 + r;
        float4 v0, v1;
        unpack2(acc[r][0], v0.x, v0.y);
        unpack2(acc[r][1], v0.z, v0.w);
        unpack2(acc[r][2], v1.x, v1.y);
        unpack2(acc[r][3], v1.z, v1.w);
        float* pp = &d_part[((size_t)ks * 2048 + row) * 128];
        *(float4*)&pp[cg * 4]      = v0;
        *(float4*)&pp[64 + cg * 4] = v1;
    }
}

__global__ void reduce_kernel() {
    int idx = blockIdx.x * 256 + threadIdx.x;   // 262144
    float s = 0.f;
#pragma unroll
    for (int k = 0; k < 18; k++) s += d_part[(size_t)k * 262144 + idx];
    d_fw[idx] = s;
}

// ------------------- mode mix + ETD coefficients (bias folded at m=0) -------------------
__global__ void __launch_bounds__(512) modemix_kernel(const float* __restrict__ mix_re,
                                                      const float* __restrict__ mix_im,
                                                      const float* __restrict__ log_decay,
                                                      const float* __restrict__ w_b,
                                                      const float* __restrict__ alpha_w,
                                                      int blk) {
    __shared__ float sg[64 * 128];
    const int b  = blockIdx.x;
    const int og = blockIdx.y;
    const int tid = threadIdx.x;
#pragma unroll
    for (int l = 0; l < 16; l++) {
        int idx = l * 512 + tid;
        sg[idx] = d_fw[(size_t)(1024 + b * 64) * 128 + idx];
    }
    __syncthreads();
    const int m = tid & 63, ol = tid >> 6;
    const int o = og * 8 + ol;
    const float* mr = mix_re + (size_t)blk * 262144 + o * 64 + m;
    const float* mi = mix_im + (size_t)blk * 262144 + o * 64 + m;
    float ar = 0.f, ai = 0.f;
#pragma unroll 4
    for (int i = 0; i < 64; i++) {
        float2 gh = *(const float2*)&sg[i * 128 + 2 * m];
        float r_ = __ldg(&mr[(size_t)i * 4096]);
        float i_ = __ldg(&mi[(size_t)i * 4096]);
        ar = fmaf(gh.x, r_, ar); ar = fmaf(-gh.y, i_, ar);
        ai = fmaf(gh.x, i_, ai); ai = fmaf( gh.y, r_, ai);
    }
    float ld = __ldg(&log_decay[((size_t)blk * 64 + o) * 64 + m]);
    float z  = -softplus_(ld);
    float ez = expf(z);
    float phi = (fabsf(z) < 1e-6f) ? (1.f + 0.5f * z + z * z * (1.f / 6.f))
                                   : (expm1f(z) / z);
    float gq = (float)m * (1.f / 63.f);
    float r2 = gq * gq + 1e-12f;
    float r8 = r2 * r2; r8 = r8 * r8;
    float pf = phi * expf(-2.f * r8);

    size_t vrow = ((size_t)b * 64 + o) * 128;
    float vr = d_fw[vrow + 2 * m], vi = d_fw[vrow + 2 * m + 1];
    float outr = fmaf(ez, vr, pf * ar);
    float outi = fmaf(ez, vi, pf * ai);
    const float inv = 1.0f / 16386.0f;
    float resr = (m == 0) ? outr * inv : 2.f * outr * inv;
    if (m == 0) resr += softplus_(__ldg(alpha_w)) * __ldg(&w_b[blk * 64 + o]);
    d_outm[vrow + 2 * m]     = resr;
    d_outm[vrow + 2 * m + 1] = (m == 0) ? 0.f : -2.f * outi * inv;
}

// ---- inverse DFT + fused w-skip + act: 8 rows x 8 x per thread (crossbar fix) ----
__global__ void __launch_bounds__(256, 2) idft_kernel(int act) {
    const int x0 = blockIdx.x * 256;
    const int b  = blockIdx.y;
    __shared__ float st[2][16][256];   // [k][x] straight (cp.async)
    __shared__ float sc[2][16][136];   // coef DUP [k][2*row]
    const int tid = threadIdx.x;
    const int xg = tid & 31;           // x chunks: xg*4 and 128+xg*4
    const int rg = tid >> 5;           // rows rg*8..+7  (0..7)
    float* hb = d_h + (size_t)b * 64 * XS;

    uint64_t acc[8][4];                // [row][j]: j0,j1 = chunk0; j2,j3 = chunk1
#pragma unroll
    for (int r = 0; r < 8; r++)
#pragma unroll
        for (int j = 0; j < 4; j++) acc[r][j] = 0ull;

    float rc[4];
    // prefetch tile 0
#pragma unroll
    for (int l = 0; l < 4; l++) {
        int c = l * 256 + tid;
        cp16(s2u(&st[0][c >> 6][(c & 63) * 4]),
             &d_itab[(size_t)(c >> 6) * XS + x0 + (c & 63) * 4]);
    }
    CP_COMMIT;
#pragma unroll
    for (int l = 0; l < 4; l++) {
        int c = l * 256 + tid;
        rc[l] = d_outm[(size_t)(b * 64 + (c >> 4)) * 128 + (c & 15)];
    }
#pragma unroll
    for (int l = 0; l < 4; l++) {
        int c = l * 256 + tid;
        *(uint64_t*)&sc[0][c & 15][2 * (c >> 4)] = pack2(rc[l], rc[l]);
    }
    CP_WAIT(0);
    __syncthreads();

#pragma unroll
    for (int t = 0; t < 12; t++) {
        const int buf = t & 1;
        if (t < 11) {
            const int kb = (t + 1) * 16;
#pragma unroll
            for (int l = 0; l < 4; l++) {
                int c = l * 256 + tid;
                int k = c >> 6, q = (c & 63) * 4;
                const float* gsrc = (kb < 128)
                    ? &d_itab[(size_t)(kb + k) * XS + x0 + q]
                    : &hb[(size_t)(kb - 128 + k) * XS + x0 + q];
                cp16(s2u(&st[buf ^ 1][k][q]), gsrc);
            }
            CP_COMMIT;
#pragma unroll
            for (int l = 0; l < 4; l++) {
                int c = l * 256 + tid;
                int k = c & 15, row = c >> 4;
                rc[l] = (kb < 128)
                    ? d_outm[(size_t)(b * 64 + row) * 128 + kb + k]
                    : d_coefW[row * 64 + (kb - 128) + k];
            }
        }
#pragma unroll
        for (int k = 0; k < 16; k++) {
            ulonglong2 w01 = *(const ulonglong2*)&sc[buf][k][rg * 16];
            ulonglong2 w23 = *(const ulonglong2*)&sc[buf][k][rg * 16 + 4];
            ulonglong2 w45 = *(const ulonglong2*)&sc[buf][k][rg * 16 + 8];
            ulonglong2 w67 = *(const ulonglong2*)&sc[buf][k][rg * 16 + 12];
            uint64_t wd[8] = {w01.x, w01.y, w23.x, w23.y, w45.x, w45.y, w67.x, w67.y};
            ulonglong2 xv0 = *(const ulonglong2*)&st[buf][k][xg * 4];
            ulonglong2 xv1 = *(const ulonglong2*)&st[buf][k][128 + xg * 4];
#pragma unroll
            for (int r = 0; r < 8; r++) {
                FMA2(acc[r][0], wd[r], xv0.x);
                FMA2(acc[r][1], wd[r], xv0.y);
                FMA2(acc[r][2], wd[r], xv1.x);
                FMA2(acc[r][3], wd[r], xv1.y);
            }
        }
        if (t < 11) {
#pragma unroll
            for (int l = 0; l < 4; l++) {
                int c = l * 256 + tid;
                *(uint64_t*)&sc[buf ^ 1][c & 15][2 * (c >> 4)] = pack2(rc[l], rc[l]);
            }
            CP_WAIT(0);
        }
        __syncthreads();
    }
#pragma unroll
    for (int r = 0; r < 8; r++) {
        int row = rg * 8 + r;
        float4 v0, v1;
        unpack2(acc[r][0], v0.x, v0.y);
        unpack2(acc[r][1], v0.z, v0.w);
        unpack2(acc[r][2], v1.x, v1.y);
        unpack2(acc[r][3], v1.z, v1.w);
        if (act) {
            v0.x = gelu_(v0.x); v0.y = gelu_(v0.y); v0.z = gelu_(v0.z); v0.w = gelu_(v0.w);
            v1.x = gelu_(v1.x); v1.y = gelu_(v1.y); v1.z = gelu_(v1.z); v1.w = gelu_(v1.w);
        }
        *(float4*)&hb[(size_t)row * XS + x0 + xg * 4]       = v0;
        *(float4*)&hb[(size_t)row * XS + x0 + 128 + xg * 4] = v1;
    }
}

// ------------------- fc2 -------------------
__global__ void __launch_bounds__(128) fc2_kernel(const float* __restrict__ w,
                                                  const float* __restrict__ bias,
                                                  float* __restrict__ out) {
    __shared__ float sw[3][128];
    int tid = threadIdx.x;
    for (int l = tid; l < 384; l += 128) sw[l >> 7][l & 127] = w[l];
    __syncthreads();
    int b = blockIdx.y;
    int x = blockIdx.x * 128 + tid;
    float a0 = __ldg(&bias[0]), a1 = __ldg(&bias[1]), a2 = __ldg(&bias[2]);
#pragma unroll 4
    for (int j = 0; j < 128; j++) {
        float v = d_gmid[((size_t)b * 128 + j) * XS + x];
        a0 = fmaf(v, sw[0][j], a0);
        a1 = fmaf(v, sw[1][j], a1);
        a2 = fmaf(v, sw[2][j], a2);
    }
    size_t o = ((size_t)b * NXV + x) * 3;
    out[o] = a0; out[o + 1] = a1; out[o + 2] = a2;
}

// ------------------- launch -------------------
extern "C" void kernel_launch(void* const* d_in, const int* in_sizes, int n_in,
                              void* d_out, int out_size) {
    const float* x_in   = (const float*)d_in[0];
    const float* grid   = (const float*)d_in[1];
    const float* fc0_w  = (const float*)d_in[2];
    const float* fc0_b  = (const float*)d_in[3];
    const float* fc1_w  = (const float*)d_in[4];
    const float* fc1_b  = (const float*)d_in[5];
    const float* fc2_w  = (const float*)d_in[6];
    const float* fc2_b  = (const float*)d_in[7];
    const float* g_w1   = (const float*)d_in[8];
    const float* g_b1   = (const float*)d_in[9];
    const float* g_w2   = (const float*)d_in[10];
    const float* g_b2   = (const float*)d_in[11];
    const float* w_w    = (const float*)d_in[12];
    const float* w_b    = (const float*)d_in[13];
    const float* ldcy   = (const float*)d_in[14];
    const float* mix_re = (const float*)d_in[15];
    const float* mix_im = (const float*)d_in[16];
    const float* aw     = (const float*)d_in[17];
    const float* ag     = (const float*)d_in[18];

    float *ph, *pg, *pgmid, *pw1T, *pw2T, *pfc1T;
    cudaGetSymbolAddress((void**)&ph,    d_h);
    cudaGetSymbolAddress((void**)&pg,    d_g);
    cudaGetSymbolAddress((void**)&pgmid, d_gmid);
    cudaGetSymbolAddress((void**)&pw1T,  d_w1T);
    cudaGetSymbolAddress((void**)&pw2T,  d_w2T);
    cudaGetSymbolAddress((void**)&pfc1T, d_fc1T);

    setup_kernel<<<18864, 256>>>(x_in, grid, fc0_w, fc0_b, g_w1, g_w2, fc1_w);

    for (int i = 0; i < 4; i++) {
        conv1x1_kernel<64, 128, 1><<<dim3(130, 16), 256>>>(
            ph, pw1T + i * 8192, g_b1 + i * 128, pgmid, nullptr);
        conv1x1_kernel<128, 64, 2><<<dim3(65, 16), 256>>>(
            pgmid, pw2T + i * 8192, g_b2 + i * 64, pg, ag);
        fdft_kernel<<<dim3(16, 18), 512>>>();
        reduce_kernel<<<1024, 256>>>();
        coefw_kernel<<<16, 256>>>(w_w, aw, i);
        modemix_kernel<<<dim3(16, 8), 512>>>(mix_re, mix_im, ldcy, w_b, aw, i);
        idft_kernel<<<dim3(65, 16), 256>>>((i < 3) ? 1 : 0);
    }

    conv1x1_kernel<64, 128, 1><<<dim3(128, 16), 256>>>(
        ph, pfc1T, fc1_b, pgmid, nullptr);
    fc2_kernel<<<dim3(128, 16), 128>>>(fc2_w, fc2_b, (float*)d_out);
}

// round 13
// speedup vs baseline: 1.0804x; 1.0804x over previous
#include <cuda_runtime.h>
#include <math.h>
#include <stdint.h>

#define XP    16386
#define XS    16640          // row stride (65*256)
#define NXV   16384
#define KPAD  16416          // forward-DFT K extent (18*912)
#define NB    16

// ------------------- static device buffers -------------------
__device__ float d_h   [(size_t)NB * 64 * XS];
__device__ float d_g   [(size_t)NB * 64 * XS];
__device__ float d_gmid[(size_t)NB * 128 * XS];
__device__ float d_ftab[(size_t)KPAD * 128];      // [x][2m]=cos, [2m+1]=-sin
__device__ float d_itab[(size_t)128 * XS];        // [2m][x]=cos, [2m+1][x]=sin
__device__ float d_part[(size_t)18 * 2048 * 128];
__device__ float d_fw  [2048 * 128];
__device__ float d_outm[1024 * 128];
__device__ float d_coefW[64 * 64];                // aw * W for current block
__device__ float d_w1T [4 * 64 * 128];
__device__ float d_w2T [4 * 128 * 64];
__device__ float d_fc1T[64 * 128];

// ------------------- f32x2 packed helpers -------------------
__device__ __forceinline__ uint64_t pack2(float lo, float hi) {
    uint64_t r;
    asm("mov.b64 %0, {%1, %2};" : "=l"(r) : "f"(lo), "f"(hi));
    return r;
}
__device__ __forceinline__ void unpack2(uint64_t v, float& lo, float& hi) {
    asm("mov.b64 {%0, %1}, %2;" : "=f"(lo), "=f"(hi) : "l"(v));
}
#define FMA2(d, a, b) \
    asm("fma.rn.f32x2 %0, %1, %2, %0;" : "+l"(d) : "l"(a), "l"(b))

__device__ __forceinline__ uint32_t s2u(const void* p) {
    return (uint32_t)__cvta_generic_to_shared(p);
}
__device__ __forceinline__ void cp16(uint32_t s, const float* g) {
    asm volatile("cp.async.cg.shared.global [%0], [%1], 16;"
                 :: "r"(s), "l"(__cvta_generic_to_global(g)));
}
#define CP_COMMIT asm volatile("cp.async.commit_group;")
#define CP_WAIT(n) asm volatile("cp.async.wait_group %0;" :: "n"(n))

__device__ __forceinline__ float softplus_(float x) {
    return (x > 20.f) ? x : log1pf(expf(x));
}
__device__ __forceinline__ float gelu_(float v) {
    return 0.5f * v * (1.0f + erff(v * 0.70710678118654752f));
}

// ------------------- mega setup kernel -------------------
__global__ void __launch_bounds__(256) setup_kernel(
    const float* __restrict__ xin, const float* __restrict__ gin,
    const float* __restrict__ fc0_w, const float* __restrict__ fc0_b,
    const float* __restrict__ g_w1, const float* __restrict__ g_w2,
    const float* __restrict__ fc1_w)
{
    const int blk = blockIdx.x;
    const int tid = threadIdx.x;
    if (blk < 1024) {                             // ---- fc0 ----
        __shared__ float sw[64 * 32];
        __shared__ float sb[64];
        for (int l = tid; l < 64 * 31; l += 256) {
            int wo = l / 31, c = l - wo * 31;
            sw[wo * 32 + c] = fc0_w[l];
        }
        if (tid < 64) sb[tid] = fc0_b[tid];
        __syncthreads();
        int b = blk >> 6;
        int x = ((blk & 63) << 8) + tid;
        float rin[31];
        const float* xi = xin + ((size_t)b * NXV + x) * 30;
#pragma unroll
        for (int c = 0; c < 30; c++) rin[c] = __ldg(&xi[c]);
        rin[30] = __ldg(&gin[(size_t)b * NXV + x]);
        for (int wo = 0; wo < 64; wo++) {
            float acc = sb[wo];
#pragma unroll
            for (int c = 0; c < 31; c++) acc = fmaf(rin[c], sw[wo * 32 + c], acc);
            d_h[(size_t)(b * 64 + wo) * XS + x] = acc;
        }
    } else if (blk < 2048) {                      // ---- zero h tail ----
        int idx = (blk - 1024) * 256 + tid;
        int row = idx >> 8, col = NXV + (idx & 255);
        d_h[(size_t)row * XS + col] = 0.f;
    } else if (blk < 2336) {                      // ---- weight transposes ----
        int idx = (blk - 2048) * 256 + tid;
        if (idx < 32768) {
            int i = idx >> 13, r = idx & 8191, c = r >> 7, j = r & 127;
            d_w1T[idx] = g_w1[(i * 128 + j) * 64 + c];
        } else if (idx < 65536) {
            int t = idx - 32768;
            int i = t >> 13, r = t & 8191, j = r >> 6, o = r & 63;
            d_w2T[t] = g_w2[(i * 64 + o) * 128 + j];
        } else if (idx < 73728) {
            int t = idx - 65536;
            int c = t >> 7, j = t & 127;
            d_fc1T[t] = fc1_w[j * 64 + c];
        }
    } else if (blk < 10544) {                     // ---- ftab ----
        int idx = (blk - 2336) * 256 + tid;
        int x = idx >> 7, t = idx & 127, m = t >> 1;
        float v = 0.f;
        if (x < XP) {
            int u = (x * m) % XP;
            float s, c;
            sincospif(2.0f * (float)u / (float)XP, &s, &c);
            v = (t & 1) ? -s : c;
        }
        d_ftab[idx] = v;
    } else {                                      // ---- itab ----
        int idx = (blk - 10544) * 256 + tid;
        int t = idx / XS, x = idx - t * XS, m = t >> 1;
        float v = 0.f;
        if (x < XP) {
            int u = (x * m) % XP;
            float s, c;
            sincospif(2.0f * (float)u / (float)XP, &s, &c);
            v = (t & 1) ? s : c;
        }
        d_itab[idx] = v;
    }
}

__global__ void coefw_kernel(const float* __restrict__ w_w,
                             const float* __restrict__ alpha_w, int blk) {
    int i = blockIdx.x * 256 + threadIdx.x;      // 4096
    d_coefW[i] = softplus_(__ldg(alpha_w)) * __ldg(&w_w[blk * 4096 + i]);
}

// ------------------- 1x1 conv (cp.async double-buffered, f32x2) -------------------
template<int CIN, int COUT, int ACT>
__global__ void __launch_bounds__(256, 2) conv1x1_kernel(
    const float* __restrict__ in,
    const float* __restrict__ wT,
    const float* __restrict__ bias,
    float* __restrict__ out,
    const float* __restrict__ alpha)
{
    constexpr int BP  = (COUT >= 128) ? 128 : 256;
    constexpr int TPp = BP / 32;
    constexpr int TOc = COUT / 8;
    constexpr int OP  = TOc / 2;
    constexpr int NTt = CIN / 16;
    constexpr int SIC = (16 * BP / 4) / 256;
    constexpr int SWC = (16 * COUT / 4) / 256;
    __shared__ float si [2][16][BP];
    __shared__ float swt[2][16][COUT];
    const int b   = blockIdx.y;
    const int p0  = blockIdx.x * BP;
    const int tid = threadIdx.x;
    const int po  = (tid & 31) * TPp;
    const int oo  = (tid >> 5) * TOc;

    const float* inb = in + (size_t)b * CIN * XS + p0;

    uint64_t acc[TPp][OP];
#pragma unroll
    for (int p = 0; p < TPp; p++)
#pragma unroll
        for (int j = 0; j < OP; j++) acc[p][j] = 0ull;

    {
#pragma unroll
        for (int l = 0; l < SIC; l++) {
            int c = l * 256 + tid;
            int k = c / (BP / 4), q = (c % (BP / 4)) * 4;
            cp16(s2u(&si[0][k][q]), inb + k * XS + q);
        }
#pragma unroll
        for (int l = 0; l < SWC; l++) {
            int c = l * 256 + tid;
            int k = c / (COUT / 4), q = (c % (COUT / 4)) * 4;
            cp16(s2u(&swt[0][k][q]), wT + k * COUT + q);
        }
        CP_COMMIT;
    }
#pragma unroll
    for (int t = 0; t < NTt; t++) {
        const int buf = t & 1;
        if (t + 1 < NTt) {
            const int c0 = (t + 1) * 16;
#pragma unroll
            for (int l = 0; l < SIC; l++) {
                int c = l * 256 + tid;
                int k = c / (BP / 4), q = (c % (BP / 4)) * 4;
                cp16(s2u(&si[buf ^ 1][k][q]), inb + (c0 + k) * XS + q);
            }
#pragma unroll
            for (int l = 0; l < SWC; l++) {
                int c = l * 256 + tid;
                int k = c / (COUT / 4), q = (c % (COUT / 4)) * 4;
                cp16(s2u(&swt[buf ^ 1][k][q]), wT + (c0 + k) * COUT + q);
            }
            CP_COMMIT;
            CP_WAIT(1);
        } else {
            CP_WAIT(0);
        }
        __syncthreads();
#pragma unroll
        for (int k = 0; k < 16; k++) {
            uint64_t pa[TPp];
#pragma unroll
            for (int u = 0; u < TPp / 4; u++) {
                float4 av = *(const float4*)&si[buf][k][po + 4 * u];
                pa[4*u+0] = pack2(av.x, av.x);
                pa[4*u+1] = pack2(av.y, av.y);
                pa[4*u+2] = pack2(av.z, av.z);
                pa[4*u+3] = pack2(av.w, av.w);
            }
#pragma unroll
            for (int j = 0; j < OP; j++) {
                uint64_t wv = *(const uint64_t*)&swt[buf][k][oo + 2 * j];
#pragma unroll
                for (int p = 0; p < TPp; p++) FMA2(acc[p][j], wv, pa[p]);
            }
        }
        __syncthreads();
    }

    float scv = 1.f;
    if (ACT == 2) scv = softplus_(__ldg(alpha));
#pragma unroll
    for (int j = 0; j < OP; j++) {
        int o0 = oo + 2 * j;
        float b0 = __ldg(&bias[o0]);
        float b1 = __ldg(&bias[o0 + 1]);
        float vlo[TPp], vhi[TPp];
#pragma unroll
        for (int p = 0; p < TPp; p++) {
            unpack2(acc[p][j], vlo[p], vhi[p]);
            vlo[p] += b0; vhi[p] += b1;
            if (ACT == 1) { vlo[p] = gelu_(vlo[p]); vhi[p] = gelu_(vhi[p]); }
            if (ACT == 2) { vlo[p] *= scv; vhi[p] *= scv; }
        }
        float* r0 = out + ((size_t)b * COUT + o0) * XS + p0 + po;
        float* r1 = r0 + XS;
#pragma unroll
        for (int q = 0; q < TPp / 4; q++) {
            *(float4*)&r0[4*q] = make_float4(vlo[4*q], vlo[4*q+1], vlo[4*q+2], vlo[4*q+3]);
            *(float4*)&r1[4*q] = make_float4(vhi[4*q], vhi[4*q+1], vhi[4*q+2], vhi[4*q+3]);
        }
    }
}

// -------- forward DFT (R9 version): 256 threads, 8 rows x 8 comps per thread --------
__global__ void __launch_bounds__(256, 2) fdft_kernel() {
    const int rt = blockIdx.x;     // 0..15 : 128-row tiles (8 h, 8 g)
    const int ks = blockIdx.y;     // 0..17 : K splits of 912 (57 tiles)
    const float* src = (rt < 8) ? d_h + (size_t)rt * 128 * XS
                                : d_g + (size_t)(rt - 8) * 128 * XS;
    const int kbase = ks * 912;

    __shared__ float sa[2][16][260];   // rows DUPLICATED: [k][2*row]
    __shared__ float sf[2][16][128];   // ftab straight [k][comp] (cp.async)
    const int tid = threadIdx.x;
    const int cg = tid & 15;
    const int rg = tid >> 4;

    uint64_t acc[8][4];
#pragma unroll
    for (int r = 0; r < 8; r++)
#pragma unroll
        for (int j = 0; j < 4; j++) acc[r][j] = 0ull;

    float ra[8];
    // prefetch tile 0
#pragma unroll
    for (int l = 0; l < 2; l++) {
        int c = l * 256 + tid;
        cp16(s2u(&sf[0][c >> 5][(c & 31) * 4]),
             &d_ftab[(size_t)(kbase + (c >> 5)) * 128 + (c & 31) * 4]);
    }
    CP_COMMIT;
#pragma unroll
    for (int l = 0; l < 8; l++) {
        int c = l * 256 + tid;
        ra[l] = src[(size_t)(c >> 4) * XS + kbase + (c & 15)];
    }
#pragma unroll
    for (int l = 0; l < 8; l++) {
        int c = l * 256 + tid;
        *(uint64_t*)&sa[0][c & 15][2 * (c >> 4)] = pack2(ra[l], ra[l]);
    }
    CP_WAIT(0);
    __syncthreads();

    for (int t = 0; t < 57; t++) {
        const int buf = t & 1;
        if (t < 56) {
            const int kb = kbase + (t + 1) * 16;
#pragma unroll
            for (int l = 0; l < 2; l++) {
                int c = l * 256 + tid;
                cp16(s2u(&sf[buf ^ 1][c >> 5][(c & 31) * 4]),
                     &d_ftab[(size_t)(kb + (c >> 5)) * 128 + (c & 31) * 4]);
            }
            CP_COMMIT;
#pragma unroll
            for (int l = 0; l < 8; l++) {
                int c = l * 256 + tid;
                ra[l] = src[(size_t)(c >> 4) * XS + kb + (c & 15)];
            }
        }
#pragma unroll
        for (int k = 0; k < 16; k++) {
            ulonglong2 c0 = *(const ulonglong2*)&sf[buf][k][cg * 4];
            ulonglong2 c1 = *(const ulonglong2*)&sf[buf][k][64 + cg * 4];
            ulonglong2 r01 = *(const ulonglong2*)&sa[buf][k][rg * 16];
            ulonglong2 r23 = *(const ulonglong2*)&sa[buf][k][rg * 16 + 4];
            ulonglong2 r45 = *(const ulonglong2*)&sa[buf][k][rg * 16 + 8];
            ulonglong2 r67 = *(const ulonglong2*)&sa[buf][k][rg * 16 + 12];
            uint64_t rd[8] = {r01.x, r01.y, r23.x, r23.y, r45.x, r45.y, r67.x, r67.y};
#pragma unroll
            for (int r = 0; r < 8; r++) {
                FMA2(acc[r][0], rd[r], c0.x);
                FMA2(acc[r][1], rd[r], c0.y);
                FMA2(acc[r][2], rd[r], c1.x);
                FMA2(acc[r][3], rd[r], c1.y);
            }
        }
        if (t < 56) {
#pragma unroll
            for (int l = 0; l < 8; l++) {
                int c = l * 256 + tid;
                *(uint64_t*)&sa[buf ^ 1][c & 15][2 * (c >> 4)] = pack2(ra[l], ra[l]);
            }
            CP_WAIT(0);
        }
        __syncthreads();
    }
#pragma unroll
    for (int r = 0; r < 8; r++) {
        int row = rt * 128 + rg * 8 + r;
        float4 v0, v1;
        unpack2(acc[r][0], v0.x, v0.y);
        unpack2(acc[r][1], v0.z, v0.w);
        unpack2(acc[r][2], v1.x, v1.y);
        unpack2(acc[r][3], v1.z, v1.w);
        float* pp = &d_part[((size_t)ks * 2048 + row) * 128];
        *(float4*)&pp[cg * 4]      = v0;
        *(float4*)&pp[64 + cg * 4] = v1;
    }
}

__global__ void reduce_kernel() {
    int idx = blockIdx.x * 256 + threadIdx.x;   // 262144
    float s = 0.f;
#pragma unroll
    for (int k = 0; k < 18; k++) s += d_part[(size_t)k * 262144 + idx];
    d_fw[idx] = s;
}

// ------------------- mode mix + ETD coefficients (bias folded at m=0) -------------------
__global__ void __launch_bounds__(512) modemix_kernel(const float* __restrict__ mix_re,
                                                      const float* __restrict__ mix_im,
                                                      const float* __restrict__ log_decay,
                                                      const float* __restrict__ w_b,
                                                      const float* __restrict__ alpha_w,
                                                      int blk) {
    __shared__ float sg[64 * 128];
    const int b  = blockIdx.x;
    const int og = blockIdx.y;
    const int tid = threadIdx.x;
#pragma unroll
    for (int l = 0; l < 16; l++) {
        int idx = l * 512 + tid;
        sg[idx] = d_fw[(size_t)(1024 + b * 64) * 128 + idx];
    }
    __syncthreads();
    const int m = tid & 63, ol = tid >> 6;
    const int o = og * 8 + ol;
    const float* mr = mix_re + (size_t)blk * 262144 + o * 64 + m;
    const float* mi = mix_im + (size_t)blk * 262144 + o * 64 + m;
    float ar = 0.f, ai = 0.f;
#pragma unroll 4
    for (int i = 0; i < 64; i++) {
        float2 gh = *(const float2*)&sg[i * 128 + 2 * m];
        float r_ = __ldg(&mr[(size_t)i * 4096]);
        float i_ = __ldg(&mi[(size_t)i * 4096]);
        ar = fmaf(gh.x, r_, ar); ar = fmaf(-gh.y, i_, ar);
        ai = fmaf(gh.x, i_, ai); ai = fmaf( gh.y, r_, ai);
    }
    float ld = __ldg(&log_decay[((size_t)blk * 64 + o) * 64 + m]);
    float z  = -softplus_(ld);
    float ez = expf(z);
    float phi = (fabsf(z) < 1e-6f) ? (1.f + 0.5f * z + z * z * (1.f / 6.f))
                                   : (expm1f(z) / z);
    float gq = (float)m * (1.f / 63.f);
    float r2 = gq * gq + 1e-12f;
    float r8 = r2 * r2; r8 = r8 * r8;
    float pf = phi * expf(-2.f * r8);

    size_t vrow = ((size_t)b * 64 + o) * 128;
    float vr = d_fw[vrow + 2 * m], vi = d_fw[vrow + 2 * m + 1];
    float outr = fmaf(ez, vr, pf * ar);
    float outi = fmaf(ez, vi, pf * ai);
    const float inv = 1.0f / 16386.0f;
    float resr = (m == 0) ? outr * inv : 2.f * outr * inv;
    if (m == 0) resr += softplus_(__ldg(alpha_w)) * __ldg(&w_b[blk * 64 + o]);
    d_outm[vrow + 2 * m]     = resr;
    d_outm[vrow + 2 * m + 1] = (m == 0) ? 0.f : -2.f * outi * inv;
}

// ---- inverse DFT + fused w-skip + act: 8 rows x 8 x per thread ----
__global__ void __launch_bounds__(256, 2) idft_kernel(int act) {
    const int x0 = blockIdx.x * 256;
    const int b  = blockIdx.y;
    __shared__ float st[2][16][256];   // [k][x] straight (cp.async)
    __shared__ float sc[2][16][136];   // coef DUP [k][2*row]
    const int tid = threadIdx.x;
    const int xg = tid & 31;           // x chunks: xg*4 and 128+xg*4
    const int rg = tid >> 5;           // rows rg*8..+7  (0..7)
    float* hb = d_h + (size_t)b * 64 * XS;

    uint64_t acc[8][4];
#pragma unroll
    for (int r = 0; r < 8; r++)
#pragma unroll
        for (int j = 0; j < 4; j++) acc[r][j] = 0ull;

    float rc[4];
    // prefetch tile 0
#pragma unroll
    for (int l = 0; l < 4; l++) {
        int c = l * 256 + tid;
        cp16(s2u(&st[0][c >> 6][(c & 63) * 4]),
             &d_itab[(size_t)(c >> 6) * XS + x0 + (c & 63) * 4]);
    }
    CP_COMMIT;
#pragma unroll
    for (int l = 0; l < 4; l++) {
        int c = l * 256 + tid;
        rc[l] = d_outm[(size_t)(b * 64 + (c >> 4)) * 128 + (c & 15)];
    }
#pragma unroll
    for (int l = 0; l < 4; l++) {
        int c = l * 256 + tid;
        *(uint64_t*)&sc[0][c & 15][2 * (c >> 4)] = pack2(rc[l], rc[l]);
    }
    CP_WAIT(0);
    __syncthreads();

#pragma unroll
    for (int t = 0; t < 12; t++) {
        const int buf = t & 1;
        if (t < 11) {
            const int kb = (t + 1) * 16;
#pragma unroll
            for (int l = 0; l < 4; l++) {
                int c = l * 256 + tid;
                int k = c >> 6, q = (c & 63) * 4;
                const float* gsrc = (kb < 128)
                    ? &d_itab[(size_t)(kb + k) * XS + x0 + q]
                    : &hb[(size_t)(kb - 128 + k) * XS + x0 + q];
                cp16(s2u(&st[buf ^ 1][k][q]), gsrc);
            }
            CP_COMMIT;
#pragma unroll
            for (int l = 0; l < 4; l++) {
                int c = l * 256 + tid;
                int k = c & 15, row = c >> 4;
                rc[l] = (kb < 128)
                    ? d_outm[(size_t)(b * 64 + row) * 128 + kb + k]
                    : d_coefW[row * 64 + (kb - 128) + k];
            }
        }
#pragma unroll
        for (int k = 0; k < 16; k++) {
            ulonglong2 w01 = *(const ulonglong2*)&sc[buf][k][rg * 16];
            ulonglong2 w23 = *(const ulonglong2*)&sc[buf][k][rg * 16 + 4];
            ulonglong2 w45 = *(const ulonglong2*)&sc[buf][k][rg * 16 + 8];
            ulonglong2 w67 = *(const ulonglong2*)&sc[buf][k][rg * 16 + 12];
            uint64_t wd[8] = {w01.x, w01.y, w23.x, w23.y, w45.x, w45.y, w67.x, w67.y};
            ulonglong2 xv0 = *(const ulonglong2*)&st[buf][k][xg * 4];
            ulonglong2 xv1 = *(const ulonglong2*)&st[buf][k][128 + xg * 4];
#pragma unroll
            for (int r = 0; r < 8; r++) {
                FMA2(acc[r][0], wd[r], xv0.x);
                FMA2(acc[r][1], wd[r], xv0.y);
                FMA2(acc[r][2], wd[r], xv1.x);
                FMA2(acc[r][3], wd[r], xv1.y);
            }
        }
        if (t < 11) {
#pragma unroll
            for (int l = 0; l < 4; l++) {
                int c = l * 256 + tid;
                *(uint64_t*)&sc[buf ^ 1][c & 15][2 * (c >> 4)] = pack2(rc[l], rc[l]);
            }
            CP_WAIT(0);
        }
        __syncthreads();
    }
#pragma unroll
    for (int r = 0; r < 8; r++) {
        int row = rg * 8 + r;
        float4 v0, v1;
        unpack2(acc[r][0], v0.x, v0.y);
        unpack2(acc[r][1], v0.z, v0.w);
        unpack2(acc[r][2], v1.x, v1.y);
        unpack2(acc[r][3], v1.z, v1.w);
        if (act) {
            v0.x = gelu_(v0.x); v0.y = gelu_(v0.y); v0.z = gelu_(v0.z); v0.w = gelu_(v0.w);
            v1.x = gelu_(v1.x); v1.y = gelu_(v1.y); v1.z = gelu_(v1.z); v1.w = gelu_(v1.w);
        }
        *(float4*)&hb[(size_t)row * XS + x0 + xg * 4]       = v0;
        *(float4*)&hb[(size_t)row * XS + x0 + 128 + xg * 4] = v1;
    }
}

// ------------------- fc2 -------------------
__global__ void __launch_bounds__(128) fc2_kernel(const float* __restrict__ w,
                                                  const float* __restrict__ bias,
                                                  float* __restrict__ out) {
    __shared__ float sw[3][128];
    int tid = threadIdx.x;
    for (int l = tid; l < 384; l += 128) sw[l >> 7][l & 127] = w[l];
    __syncthreads();
    int b = blockIdx.y;
    int x = blockIdx.x * 128 + tid;
    float a0 = __ldg(&bias[0]), a1 = __ldg(&bias[1]), a2 = __ldg(&bias[2]);
#pragma unroll 4
    for (int j = 0; j < 128; j++) {
        float v = d_gmid[((size_t)b * 128 + j) * XS + x];
        a0 = fmaf(v, sw[0][j], a0);
        a1 = fmaf(v, sw[1][j], a1);
        a2 = fmaf(v, sw[2][j], a2);
    }
    size_t o = ((size_t)b * NXV + x) * 3;
    out[o] = a0; out[o + 1] = a1; out[o + 2] = a2;
}

// ------------------- launch -------------------
extern "C" void kernel_launch(void* const* d_in, const int* in_sizes, int n_in,
                              void* d_out, int out_size) {
    const float* x_in   = (const float*)d_in[0];
    const float* grid   = (const float*)d_in[1];
    const float* fc0_w  = (const float*)d_in[2];
    const float* fc0_b  = (const float*)d_in[3];
    const float* fc1_w  = (const float*)d_in[4];
    const float* fc1_b  = (const float*)d_in[5];
    const float* fc2_w  = (const float*)d_in[6];
    const float* fc2_b  = (const float*)d_in[7];
    const float* g_w1   = (const float*)d_in[8];
    const float* g_b1   = (const float*)d_in[9];
    const float* g_w2   = (const float*)d_in[10];
    const float* g_b2   = (const float*)d_in[11];
    const float* w_w    = (const float*)d_in[12];
    const float* w_b    = (const float*)d_in[13];
    const float* ldcy   = (const float*)d_in[14];
    const float* mix_re = (const float*)d_in[15];
    const float* mix_im = (const float*)d_in[16];
    const float* aw     = (const float*)d_in[17];
    const float* ag     = (const float*)d_in[18];

    float *ph, *pg, *pgmid, *pw1T, *pw2T, *pfc1T;
    cudaGetSymbolAddress((void**)&ph,    d_h);
    cudaGetSymbolAddress((void**)&pg,    d_g);
    cudaGetSymbolAddress((void**)&pgmid, d_gmid);
    cudaGetSymbolAddress((void**)&pw1T,  d_w1T);
    cudaGetSymbolAddress((void**)&pw2T,  d_w2T);
    cudaGetSymbolAddress((void**)&pfc1T, d_fc1T);

    setup_kernel<<<18864, 256>>>(x_in, grid, fc0_w, fc0_b, g_w1, g_w2, fc1_w);

    for (int i = 0; i < 4; i++) {
        conv1x1_kernel<64, 128, 1><<<dim3(130, 16), 256>>>(
            ph, pw1T + i * 8192, g_b1 + i * 128, pgmid, nullptr);
        conv1x1_kernel<128, 64, 2><<<dim3(65, 16), 256>>>(
            pgmid, pw2T + i * 8192, g_b2 + i * 64, pg, ag);
        fdft_kernel<<<dim3(16, 18), 256>>>();
        reduce_kernel<<<1024, 256>>>();
        coefw_kernel<<<16, 256>>>(w_w, aw, i);
        modemix_kernel<<<dim3(16, 8), 512>>>(mix_re, mix_im, ldcy, w_b, aw, i);
        idft_kernel<<<dim3(65, 16), 256>>>((i < 3) ? 1 : 0);
    }

    conv1x1_kernel<64, 128, 1><<<dim3(128, 16), 256>>>(
        ph, pfc1T, fc1_b, pgmid, nullptr);
    fc2_kernel<<<dim3(128, 16), 128>>>(fc2_w, fc2_b, (float*)d_out);
}

// round 15
// speedup vs baseline: 1.2644x; 1.1703x over previous
#include <cuda_runtime.h>
#include <cuda_bf16.h>
#include <math.h>
#include <stdint.h>

#define XP    16386
#define XS    16640          // row stride (65*256)
#define NXV   16384
#define NB    16
#define NCHT  513            // 32-wide K chunks (513*32 = 16416 >= XP)

// ------------------- static device buffers -------------------
__device__ float d_h   [(size_t)NB * 64 * XS];
__device__ float d_g   [(size_t)NB * 64 * XS];
__device__ float d_gmid[(size_t)NB * 128 * XS];
__device__ __nv_bfloat16 d_bHi[(size_t)NCHT * 128 * 32];  // ftab^T hi [chunk][n][k]
__device__ __nv_bfloat16 d_bLo[(size_t)NCHT * 128 * 32];  // ftab^T lo
__device__ float d_itab[(size_t)128 * XS];                // [2m][x]
__device__ float d_part[(size_t)16 * 2048 * 128];
__device__ float d_fw  [2048 * 128];
__device__ float d_outm[1024 * 128];
__device__ float d_coefW[64 * 64];
__device__ float d_w1T [4 * 64 * 128];
__device__ float d_w2T [4 * 128 * 64];
__device__ float d_fc1T[64 * 128];

// ------------------- f32x2 packed helpers -------------------
__device__ __forceinline__ uint64_t pack2(float lo, float hi) {
    uint64_t r;
    asm("mov.b64 %0, {%1, %2};" : "=l"(r) : "f"(lo), "f"(hi));
    return r;
}
__device__ __forceinline__ void unpack2(uint64_t v, float& lo, float& hi) {
    asm("mov.b64 {%0, %1}, %2;" : "=f"(lo), "=f"(hi) : "l"(v));
}
#define FMA2(d, a, b) \
    asm("fma.rn.f32x2 %0, %1, %2, %0;" : "+l"(d) : "l"(a), "l"(b))

__device__ __forceinline__ uint32_t s2u(const void* p) {
    return (uint32_t)__cvta_generic_to_shared(p);
}
__device__ __forceinline__ void cp16(uint32_t s, const void* g) {
    asm volatile("cp.async.cg.shared.global [%0], [%1], 16;"
                 :: "r"(s), "l"(__cvta_generic_to_global(g)));
}
#define CP_COMMIT asm volatile("cp.async.commit_group;")
#define CP_WAIT(n) asm volatile("cp.async.wait_group %0;" :: "n"(n))

__device__ __forceinline__ float softplus_(float x) {
    return (x > 20.f) ? x : log1pf(expf(x));
}
__device__ __forceinline__ float gelu_(float v) {
    return 0.5f * v * (1.0f + erff(v * 0.70710678118654752f));
}

// ------------------- warp MMA helpers -------------------
__device__ __forceinline__ void ldsm_x4(uint32_t& r0, uint32_t& r1,
                                        uint32_t& r2, uint32_t& r3, uint32_t addr) {
    asm volatile("ldmatrix.sync.aligned.m8n8.x4.shared.b16 {%0,%1,%2,%3}, [%4];"
                 : "=r"(r0), "=r"(r1), "=r"(r2), "=r"(r3) : "r"(addr));
}
__device__ __forceinline__ void mma_bf16(float* c, const uint32_t* a,
                                         uint32_t b0, uint32_t b1) {
    asm volatile("mma.sync.aligned.m16n8k16.row.col.f32.bf16.bf16.f32 "
                 "{%0,%1,%2,%3}, {%4,%5,%6,%7}, {%8,%9}, {%0,%1,%2,%3};"
                 : "+f"(c[0]), "+f"(c[1]), "+f"(c[2]), "+f"(c[3])
                 : "r"(a[0]), "r"(a[1]), "r"(a[2]), "r"(a[3]), "r"(b0), "r"(b1));
}

// ------------------- mega setup kernel -------------------
// [0,1024) fc0 | [1024,2048) zero tail | [2048,2336) weight transposes
// [2336,10544) bf16 ftab^T hi/lo | [10544,18864) itab
__global__ void __launch_bounds__(256) setup_kernel(
    const float* __restrict__ xin, const float* __restrict__ gin,
    const float* __restrict__ fc0_w, const float* __restrict__ fc0_b,
    const float* __restrict__ g_w1, const float* __restrict__ g_w2,
    const float* __restrict__ fc1_w)
{
    const int blk = blockIdx.x;
    const int tid = threadIdx.x;
    if (blk < 1024) {                             // ---- fc0 ----
        __shared__ float sw[64 * 32];
        __shared__ float sb[64];
        for (int l = tid; l < 64 * 31; l += 256) {
            int wo = l / 31, c = l - wo * 31;
            sw[wo * 32 + c] = fc0_w[l];
        }
        if (tid < 64) sb[tid] = fc0_b[tid];
        __syncthreads();
        int b = blk >> 6;
        int x = ((blk & 63) << 8) + tid;
        float rin[31];
        const float* xi = xin + ((size_t)b * NXV + x) * 30;
#pragma unroll
        for (int c = 0; c < 30; c++) rin[c] = __ldg(&xi[c]);
        rin[30] = __ldg(&gin[(size_t)b * NXV + x]);
        for (int wo = 0; wo < 64; wo++) {
            float acc = sb[wo];
#pragma unroll
            for (int c = 0; c < 31; c++) acc = fmaf(rin[c], sw[wo * 32 + c], acc);
            d_h[(size_t)(b * 64 + wo) * XS + x] = acc;
        }
    } else if (blk < 2048) {                      // ---- zero h tail ----
        int idx = (blk - 1024) * 256 + tid;
        int row = idx >> 8, col = NXV + (idx & 255);
        d_h[(size_t)row * XS + col] = 0.f;
    } else if (blk < 2336) {                      // ---- weight transposes ----
        int idx = (blk - 2048) * 256 + tid;
        if (idx < 32768) {
            int i = idx >> 13, r = idx & 8191, c = r >> 7, j = r & 127;
            d_w1T[idx] = g_w1[(i * 128 + j) * 64 + c];
        } else if (idx < 65536) {
            int t = idx - 32768;
            int i = t >> 13, r = t & 8191, j = r >> 6, o = r & 63;
            d_w2T[t] = g_w2[(i * 64 + o) * 128 + j];
        } else if (idx < 73728) {
            int t = idx - 65536;
            int c = t >> 7, j = t & 127;
            d_fc1T[t] = fc1_w[j * 64 + c];
        }
    } else if (blk < 10544) {                     // ---- bf16 ftab^T (plain) ----
        int idx = (blk - 2336) * 256 + tid;       // 513*4096 = 2101248
        int c = idx >> 12;                        // chunk
        int e = idx & 4095;
        int n = e >> 5, k = e & 31;               // comp row, k within chunk
        int x = c * 32 + k;
        float v = 0.f;
        if (x < XP) {
            int u = (x * (n >> 1)) % XP;
            float s, co;
            sincospif(2.0f * (float)u / (float)XP, &s, &co);
            v = (n & 1) ? -s : co;
        }
        __nv_bfloat16 hi = __float2bfloat16(v);
        __nv_bfloat16 lo = __float2bfloat16(v - __bfloat162float(hi));
        d_bHi[idx] = hi;
        d_bLo[idx] = lo;
    } else {                                      // ---- itab ----
        int idx = (blk - 10544) * 256 + tid;
        int t = idx / XS, x = idx - t * XS, m = t >> 1;
        float v = 0.f;
        if (x < XP) {
            int u = (x * m) % XP;
            float s, c;
            sincospif(2.0f * (float)u / (float)XP, &s, &c);
            v = (t & 1) ? s : c;
        }
        d_itab[idx] = v;
    }
}

__global__ void coefw_kernel(const float* __restrict__ w_w,
                             const float* __restrict__ alpha_w, int blk) {
    int i = blockIdx.x * 256 + threadIdx.x;      // 4096
    d_coefW[i] = softplus_(__ldg(alpha_w)) * __ldg(&w_w[blk * 4096 + i]);
}

// ------------------- 1x1 conv (cp.async double-buffered, f32x2) -------------------
template<int CIN, int COUT, int ACT>
__global__ void __launch_bounds__(256, 2) conv1x1_kernel(
    const float* __restrict__ in,
    const float* __restrict__ wT,
    const float* __restrict__ bias,
    float* __restrict__ out,
    const float* __restrict__ alpha)
{
    constexpr int BP  = (COUT >= 128) ? 128 : 256;
    constexpr int TPp = BP / 32;
    constexpr int TOc = COUT / 8;
    constexpr int OP  = TOc / 2;
    constexpr int NTt = CIN / 16;
    constexpr int SIC = (16 * BP / 4) / 256;
    constexpr int SWC = (16 * COUT / 4) / 256;
    __shared__ float si [2][16][BP];
    __shared__ float swt[2][16][COUT];
    const int b   = blockIdx.y;
    const int p0  = blockIdx.x * BP;
    const int tid = threadIdx.x;
    const int po  = (tid & 31) * TPp;
    const int oo  = (tid >> 5) * TOc;

    const float* inb = in + (size_t)b * CIN * XS + p0;

    uint64_t acc[TPp][OP];
#pragma unroll
    for (int p = 0; p < TPp; p++)
#pragma unroll
        for (int j = 0; j < OP; j++) acc[p][j] = 0ull;

    {
#pragma unroll
        for (int l = 0; l < SIC; l++) {
            int c = l * 256 + tid;
            int k = c / (BP / 4), q = (c % (BP / 4)) * 4;
            cp16(s2u(&si[0][k][q]), inb + k * XS + q);
        }
#pragma unroll
        for (int l = 0; l < SWC; l++) {
            int c = l * 256 + tid;
            int k = c / (COUT / 4), q = (c % (COUT / 4)) * 4;
            cp16(s2u(&swt[0][k][q]), wT + k * COUT + q);
        }
        CP_COMMIT;
    }
#pragma unroll
    for (int t = 0; t < NTt; t++) {
        const int buf = t & 1;
        if (t + 1 < NTt) {
            const int c0 = (t + 1) * 16;
#pragma unroll
            for (int l = 0; l < SIC; l++) {
                int c = l * 256 + tid;
                int k = c / (BP / 4), q = (c % (BP / 4)) * 4;
                cp16(s2u(&si[buf ^ 1][k][q]), inb + (c0 + k) * XS + q);
            }
#pragma unroll
            for (int l = 0; l < SWC; l++) {
                int c = l * 256 + tid;
                int k = c / (COUT / 4), q = (c % (COUT / 4)) * 4;
                cp16(s2u(&swt[buf ^ 1][k][q]), wT + (c0 + k) * COUT + q);
            }
            CP_COMMIT;
            CP_WAIT(1);
        } else {
            CP_WAIT(0);
        }
        __syncthreads();
#pragma unroll
        for (int k = 0; k < 16; k++) {
            uint64_t pa[TPp];
#pragma unroll
            for (int u = 0; u < TPp / 4; u++) {
                float4 av = *(const float4*)&si[buf][k][po + 4 * u];
                pa[4*u+0] = pack2(av.x, av.x);
                pa[4*u+1] = pack2(av.y, av.y);
                pa[4*u+2] = pack2(av.z, av.z);
                pa[4*u+3] = pack2(av.w, av.w);
            }
#pragma unroll
            for (int j = 0; j < OP; j++) {
                uint64_t wv = *(const uint64_t*)&swt[buf][k][oo + 2 * j];
#pragma unroll
                for (int p = 0; p < TPp; p++) FMA2(acc[p][j], wv, pa[p]);
            }
        }
        __syncthreads();
    }

    float scv = 1.f;
    if (ACT == 2) scv = softplus_(__ldg(alpha));
#pragma unroll
    for (int j = 0; j < OP; j++) {
        int o0 = oo + 2 * j;
        float b0 = __ldg(&bias[o0]);
        float b1 = __ldg(&bias[o0 + 1]);
        float vlo[TPp], vhi[TPp];
#pragma unroll
        for (int p = 0; p < TPp; p++) {
            unpack2(acc[p][j], vlo[p], vhi[p]);
            vlo[p] += b0; vhi[p] += b1;
            if (ACT == 1) { vlo[p] = gelu_(vlo[p]); vhi[p] = gelu_(vhi[p]); }
            if (ACT == 2) { vlo[p] *= scv; vhi[p] *= scv; }
        }
        float* r0 = out + ((size_t)b * COUT + o0) * XS + p0 + po;
        float* r1 = r0 + XS;
#pragma unroll
        for (int q = 0; q < TPp / 4; q++) {
            *(float4*)&r0[4*q] = make_float4(vlo[4*q], vlo[4*q+1], vlo[4*q+2], vlo[4*q+3]);
            *(float4*)&r1[4*q] = make_float4(vhi[4*q], vhi[4*q+1], vhi[4*q+2], vhi[4*q+3]);
        }
    }
}

// ------------- forward DFT via warp-level split-bf16 mma.sync -------------
// D[128 rows][128 comps] = sum_k A[row][k] * Bt[comp][k]
// A split hi/lo in smem [row][PAD] bf16; B pre-split in gmem, staged [n][PAD].
#define PAD 40                  // padded row length (bf16 elems), 80 bytes
#define OFF_STAGE 0             // 128*32*4   = 16384
#define OFF_AHI   16384         // 128*80     = 10240
#define OFF_ALO   26624
#define OFF_B     36864         // 2 bufs x (hi+lo) x 10240 = 40960
#define SMEM_FDFT 77824

__global__ void __launch_bounds__(256, 2) fdft_kernel() {
    extern __shared__ char smem[];
    const uint32_t sb = s2u(smem);
    const int tid = threadIdx.x;
    const int wid = tid >> 5, lane = tid & 31;
    const int rt = blockIdx.x;     // 0..15 : 128-row tiles (8 h, 8 g)
    const int ks = blockIdx.y;     // 0..15 : chunk splits
    const float* src = (rt < 8) ? d_h + (size_t)rt * 128 * XS
                                : d_g + (size_t)(rt - 8) * 128 * XS;
    const int ch0 = ks * 32;
    const int nch = (ks == 15) ? 33 : 32;

    const int wm = (wid >> 1) * 32;    // warp row base
    const int wn = (wid & 1) * 64;     // warp comp base

    float acc[2][8][4];
#pragma unroll
    for (int mt = 0; mt < 2; mt++)
#pragma unroll
        for (int nt = 0; nt < 8; nt++)
#pragma unroll
            for (int j = 0; j < 4; j++) acc[mt][nt][j] = 0.f;

    // ---- prologue: stage chunk 0 ----
    {
        const int xb = ch0 * 32;
#pragma unroll
        for (int l = 0; l < 4; l++) {
            int c = l * 256 + tid;                 // [0,1024): row=c>>3, q=c&7
            cp16(sb + OFF_STAGE + c * 16,
                 src + (size_t)(c >> 3) * XS + xb + (c & 7) * 4);
        }
#pragma unroll
        for (int l = 0; l < 2; l++) {
            int c = l * 256 + tid;                 // [0,512): row=c>>2, q=c&3
            int row = c >> 2, q = c & 3;
            cp16(sb + OFF_B + row * 80 + q * 16,
                 d_bHi + (size_t)ch0 * 4096 + row * 32 + q * 8);
            cp16(sb + OFF_B + 10240 + row * 80 + q * 16,
                 d_bLo + (size_t)ch0 * 4096 + row * 32 + q * 8);
        }
        CP_COMMIT;
        CP_WAIT(0);
        __syncthreads();
        // convert stage -> Ahi/Alo
#pragma unroll
        for (int l = 0; l < 8; l++) {
            int idx = l * 256 + tid;               // [0,2048): row=idx>>4, kp=idx&15
            int row = idx >> 4, kp = idx & 15;
            float2 v = *(const float2*)(smem + OFF_STAGE + (row * 32 + kp * 2) * 4);
            __nv_bfloat16 h0 = __float2bfloat16(v.x);
            __nv_bfloat16 h1 = __float2bfloat16(v.y);
            __nv_bfloat16 l0 = __float2bfloat16(v.x - __bfloat162float(h0));
            __nv_bfloat16 l1 = __float2bfloat16(v.y - __bfloat162float(h1));
            uint32_t hw = (uint32_t)__bfloat16_as_ushort(h0)
                        | ((uint32_t)__bfloat16_as_ushort(h1) << 16);
            uint32_t lw = (uint32_t)__bfloat16_as_ushort(l0)
                        | ((uint32_t)__bfloat16_as_ushort(l1) << 16);
            *(uint32_t*)(smem + OFF_AHI + row * 80 + kp * 4) = hw;
            *(uint32_t*)(smem + OFF_ALO + row * 80 + kp * 4) = lw;
        }
        __syncthreads();
    }

    for (int t = 0; t < nch; t++) {
        const int buf = t & 1;
        if (t + 1 < nch) {
            const int xb = (ch0 + t + 1) * 32;
#pragma unroll
            for (int l = 0; l < 4; l++) {
                int c = l * 256 + tid;
                cp16(sb + OFF_STAGE + c * 16,
                     src + (size_t)(c >> 3) * XS + xb + (c & 7) * 4);
            }
            const uint32_t bo = OFF_B + (buf ^ 1) * 20480;
#pragma unroll
            for (int l = 0; l < 2; l++) {
                int c = l * 256 + tid;
                int row = c >> 2, q = c & 3;
                cp16(sb + bo + row * 80 + q * 16,
                     d_bHi + (size_t)(ch0 + t + 1) * 4096 + row * 32 + q * 8);
                cp16(sb + bo + 10240 + row * 80 + q * 16,
                     d_bLo + (size_t)(ch0 + t + 1) * 4096 + row * 32 + q * 8);
            }
            CP_COMMIT;
        }
        // ---- compute chunk t ----
        const uint32_t bhB = sb + OFF_B + buf * 20480;
        const uint32_t blB = bhB + 10240;
#pragma unroll
        for (int k16 = 0; k16 < 2; k16++) {
            const int kc = k16 * 16 + ((lane >> 4) << 3);   // A frag col
            uint32_t ah[2][4], al[2][4];
#pragma unroll
            for (int mt = 0; mt < 2; mt++) {
                uint32_t aaddr = sb + OFF_AHI + (wm + mt * 16 + (lane & 15)) * 80 + kc * 2;
                ldsm_x4(ah[mt][0], ah[mt][1], ah[mt][2], ah[mt][3], aaddr);
                uint32_t laddr = sb + OFF_ALO + (wm + mt * 16 + (lane & 15)) * 80 + kc * 2;
                ldsm_x4(al[mt][0], al[mt][1], al[mt][2], al[mt][3], laddr);
            }
            const int brow = (lane & 7) + ((lane >> 4) << 3);
            const int bcol = k16 * 16 + (((lane >> 3) & 1) << 3);
#pragma unroll
            for (int p = 0; p < 4; p++) {
                uint32_t bh0, bh1, bh2, bh3, bl0, bl1, bl2, bl3;
                uint32_t off = (uint32_t)(wn + p * 16 + brow) * 80 + bcol * 2;
                ldsm_x4(bh0, bh1, bh2, bh3, bhB + off);
                ldsm_x4(bl0, bl1, bl2, bl3, blB + off);
#pragma unroll
                for (int mt = 0; mt < 2; mt++) {
                    mma_bf16(acc[mt][2 * p],     ah[mt], bh0, bh1);
                    mma_bf16(acc[mt][2 * p + 1], ah[mt], bh2, bh3);
                    mma_bf16(acc[mt][2 * p],     ah[mt], bl0, bl1);
                    mma_bf16(acc[mt][2 * p + 1], ah[mt], bl2, bl3);
                    mma_bf16(acc[mt][2 * p],     al[mt], bh0, bh1);
                    mma_bf16(acc[mt][2 * p + 1], al[mt], bh2, bh3);
                }
            }
        }
        if (t + 1 < nch) {
            CP_WAIT(0);
            __syncthreads();
#pragma unroll
            for (int l = 0; l < 8; l++) {
                int idx = l * 256 + tid;
                int row = idx >> 4, kp = idx & 15;
                float2 v = *(const float2*)(smem + OFF_STAGE + (row * 32 + kp * 2) * 4);
                __nv_bfloat16 h0 = __float2bfloat16(v.x);
                __nv_bfloat16 h1 = __float2bfloat16(v.y);
                __nv_bfloat16 l0 = __float2bfloat16(v.x - __bfloat162float(h0));
                __nv_bfloat16 l1 = __float2bfloat16(v.y - __bfloat162float(h1));
                uint32_t hw = (uint32_t)__bfloat16_as_ushort(h0)
                            | ((uint32_t)__bfloat16_as_ushort(h1) << 16);
                uint32_t lw = (uint32_t)__bfloat16_as_ushort(l0)
                            | ((uint32_t)__bfloat16_as_ushort(l1) << 16);
                *(uint32_t*)(smem + OFF_AHI + row * 80 + kp * 4) = hw;
                *(uint32_t*)(smem + OFF_ALO + row * 80 + kp * 4) = lw;
            }
            __syncthreads();
        }
    }

    // ---- epilogue: write partials ----
#pragma unroll
    for (int mt = 0; mt < 2; mt++)
#pragma unroll
        for (int nt = 0; nt < 8; nt++) {
            int row = rt * 128 + wm + mt * 16 + (lane >> 2);
            int col = wn + nt * 8 + (lane & 3) * 2;
            size_t base = ((size_t)ks * 2048 + row) * 128 + col;
            *(float2*)&d_part[base] = make_float2(acc[mt][nt][0], acc[mt][nt][1]);
            *(float2*)&d_part[base + 8 * 128] = make_float2(acc[mt][nt][2], acc[mt][nt][3]);
        }
}

__global__ void reduce_kernel() {
    int idx = blockIdx.x * 256 + threadIdx.x;   // 262144
    float s = 0.f;
#pragma unroll
    for (int k = 0; k < 16; k++) s += d_part[(size_t)k * 262144 + idx];
    d_fw[idx] = s;
}

// ------------------- mode mix + ETD coefficients (bias folded at m=0) -------------------
__global__ void __launch_bounds__(512) modemix_kernel(const float* __restrict__ mix_re,
                                                      const float* __restrict__ mix_im,
                                                      const float* __restrict__ log_decay,
                                                      const float* __restrict__ w_b,
                                                      const float* __restrict__ alpha_w,
                                                      int blk) {
    __shared__ float sg[64 * 128];
    const int b  = blockIdx.x;
    const int og = blockIdx.y;
    const int tid = threadIdx.x;
#pragma unroll
    for (int l = 0; l < 16; l++) {
        int idx = l * 512 + tid;
        sg[idx] = d_fw[(size_t)(1024 + b * 64) * 128 + idx];
    }
    __syncthreads();
    const int m = tid & 63, ol = tid >> 6;
    const int o = og * 8 + ol;
    const float* mr = mix_re + (size_t)blk * 262144 + o * 64 + m;
    const float* mi = mix_im + (size_t)blk * 262144 + o * 64 + m;
    float ar = 0.f, ai = 0.f;
#pragma unroll 4
    for (int i = 0; i < 64; i++) {
        float2 gh = *(const float2*)&sg[i * 128 + 2 * m];
        float r_ = __ldg(&mr[(size_t)i * 4096]);
        float i_ = __ldg(&mi[(size_t)i * 4096]);
        ar = fmaf(gh.x, r_, ar); ar = fmaf(-gh.y, i_, ar);
        ai = fmaf(gh.x, i_, ai); ai = fmaf( gh.y, r_, ai);
    }
    float ld = __ldg(&log_decay[((size_t)blk * 64 + o) * 64 + m]);
    float z  = -softplus_(ld);
    float ez = expf(z);
    float phi = (fabsf(z) < 1e-6f) ? (1.f + 0.5f * z + z * z * (1.f / 6.f))
                                   : (expm1f(z) / z);
    float gq = (float)m * (1.f / 63.f);
    float r2 = gq * gq + 1e-12f;
    float r8 = r2 * r2; r8 = r8 * r8;
    float pf = phi * expf(-2.f * r8);

    size_t vrow = ((size_t)b * 64 + o) * 128;
    float vr = d_fw[vrow + 2 * m], vi = d_fw[vrow + 2 * m + 1];
    float outr = fmaf(ez, vr, pf * ar);
    float outi = fmaf(ez, vi, pf * ai);
    const float inv = 1.0f / 16386.0f;
    float resr = (m == 0) ? outr * inv : 2.f * outr * inv;
    if (m == 0) resr += softplus_(__ldg(alpha_w)) * __ldg(&w_b[blk * 64 + o]);
    d_outm[vrow + 2 * m]     = resr;
    d_outm[vrow + 2 * m + 1] = (m == 0) ? 0.f : -2.f * outi * inv;
}

// ---- inverse DFT + fused w-skip + act: 8 rows x 8 x per thread ----
__global__ void __launch_bounds__(256, 2) idft_kernel(int act) {
    const int x0 = blockIdx.x * 256;
    const int b  = blockIdx.y;
    __shared__ float st[2][16][256];
    __shared__ float sc[2][16][136];
    const int tid = threadIdx.x;
    const int xg = tid & 31;
    const int rg = tid >> 5;
    float* hb = d_h + (size_t)b * 64 * XS;

    uint64_t acc[8][4];
#pragma unroll
    for (int r = 0; r < 8; r++)
#pragma unroll
        for (int j = 0; j < 4; j++) acc[r][j] = 0ull;

    float rc[4];
#pragma unroll
    for (int l = 0; l < 4; l++) {
        int c = l * 256 + tid;
        cp16(s2u(&st[0][c >> 6][(c & 63) * 4]),
             &d_itab[(size_t)(c >> 6) * XS + x0 + (c & 63) * 4]);
    }
    CP_COMMIT;
#pragma unroll
    for (int l = 0; l < 4; l++) {
        int c = l * 256 + tid;
        rc[l] = d_outm[(size_t)(b * 64 + (c >> 4)) * 128 + (c & 15)];
    }
#pragma unroll
    for (int l = 0; l < 4; l++) {
        int c = l * 256 + tid;
        *(uint64_t*)&sc[0][c & 15][2 * (c >> 4)] = pack2(rc[l], rc[l]);
    }
    CP_WAIT(0);
    __syncthreads();

#pragma unroll
    for (int t = 0; t < 12; t++) {
        const int buf = t & 1;
        if (t < 11) {
            const int kb = (t + 1) * 16;
#pragma unroll
            for (int l = 0; l < 4; l++) {
                int c = l * 256 + tid;
                int k = c >> 6, q = (c & 63) * 4;
                const float* gsrc = (kb < 128)
                    ? &d_itab[(size_t)(kb + k) * XS + x0 + q]
                    : &hb[(size_t)(kb - 128 + k) * XS + x0 + q];
                cp16(s2u(&st[buf ^ 1][k][q]), gsrc);
            }
            CP_COMMIT;
#pragma unroll
            for (int l = 0; l < 4; l++) {
                int c = l * 256 + tid;
                int k = c & 15, row = c >> 4;
                rc[l] = (kb < 128)
                    ? d_outm[(size_t)(b * 64 + row) * 128 + kb + k]
                    : d_coefW[row * 64 + (kb - 128) + k];
            }
        }
#pragma unroll
        for (int k = 0; k < 16; k++) {
            ulonglong2 w01 = *(const ulonglong2*)&sc[buf][k][rg * 16];
            ulonglong2 w23 = *(const ulonglong2*)&sc[buf][k][rg * 16 + 4];
            ulonglong2 w45 = *(const ulonglong2*)&sc[buf][k][rg * 16 + 8];
            ulonglong2 w67 = *(const ulonglong2*)&sc[buf][k][rg * 16 + 12];
            uint64_t wd[8] = {w01.x, w01.y, w23.x, w23.y, w45.x, w45.y, w67.x, w67.y};
            ulonglong2 xv0 = *(const ulonglong2*)&st[buf][k][xg * 4];
            ulonglong2 xv1 = *(const ulonglong2*)&st[buf][k][128 + xg * 4];
#pragma unroll
            for (int r = 0; r < 8; r++) {
                FMA2(acc[r][0], wd[r], xv0.x);
                FMA2(acc[r][1], wd[r], xv0.y);
                FMA2(acc[r][2], wd[r], xv1.x);
                FMA2(acc[r][3], wd[r], xv1.y);
            }
        }
        if (t < 11) {
#pragma unroll
            for (int l = 0; l < 4; l++) {
                int c = l * 256 + tid;
                *(uint64_t*)&sc[buf ^ 1][c & 15][2 * (c >> 4)] = pack2(rc[l], rc[l]);
            }
            CP_WAIT(0);
        }
        __syncthreads();
    }
#pragma unroll
    for (int r = 0; r < 8; r++) {
        int row = rg * 8 + r;
        float4 v0, v1;
        unpack2(acc[r][0], v0.x, v0.y);
        unpack2(acc[r][1], v0.z, v0.w);
        unpack2(acc[r][2], v1.x, v1.y);
        unpack2(acc[r][3], v1.z, v1.w);
        if (act) {
            v0.x = gelu_(v0.x); v0.y = gelu_(v0.y); v0.z = gelu_(v0.z); v0.w = gelu_(v0.w);
            v1.x = gelu_(v1.x); v1.y = gelu_(v1.y); v1.z = gelu_(v1.z); v1.w = gelu_(v1.w);
        }
        *(float4*)&hb[(size_t)row * XS + x0 + xg * 4]       = v0;
        *(float4*)&hb[(size_t)row * XS + x0 + 128 + xg * 4] = v1;
    }
}

// ------------------- fc2 -------------------
__global__ void __launch_bounds__(128) fc2_kernel(const float* __restrict__ w,
                                                  const float* __restrict__ bias,
                                                  float* __restrict__ out) {
    __shared__ float sw[3][128];
    int tid = threadIdx.x;
    for (int l = tid; l < 384; l += 128) sw[l >> 7][l & 127] = w[l];
    __syncthreads();
    int b = blockIdx.y;
    int x = blockIdx.x * 128 + tid;
    float a0 = __ldg(&bias[0]), a1 = __ldg(&bias[1]), a2 = __ldg(&bias[2]);
#pragma unroll 4
    for (int j = 0; j < 128; j++) {
        float v = d_gmid[((size_t)b * 128 + j) * XS + x];
        a0 = fmaf(v, sw[0][j], a0);
        a1 = fmaf(v, sw[1][j], a1);
        a2 = fmaf(v, sw[2][j], a2);
    }
    size_t o = ((size_t)b * NXV + x) * 3;
    out[o] = a0; out[o + 1] = a1; out[o + 2] = a2;
}

// ------------------- launch -------------------
extern "C" void kernel_launch(void* const* d_in, const int* in_sizes, int n_in,
                              void* d_out, int out_size) {
    const float* x_in   = (const float*)d_in[0];
    const float* grid   = (const float*)d_in[1];
    const float* fc0_w  = (const float*)d_in[2];
    const float* fc0_b  = (const float*)d_in[3];
    const float* fc1_w  = (const float*)d_in[4];
    const float* fc1_b  = (const float*)d_in[5];
    const float* fc2_w  = (const float*)d_in[6];
    const float* fc2_b  = (const float*)d_in[7];
    const float* g_w1   = (const float*)d_in[8];
    const float* g_b1   = (const float*)d_in[9];
    const float* g_w2   = (const float*)d_in[10];
    const float* g_b2   = (const float*)d_in[11];
    const float* w_w    = (const float*)d_in[12];
    const float* w_b    = (const float*)d_in[13];
    const float* ldcy   = (const float*)d_in[14];
    const float* mix_re = (const float*)d_in[15];
    const float* mix_im = (const float*)d_in[16];
    const float* aw     = (const float*)d_in[17];
    const float* ag     = (const float*)d_in[18];

    float *ph, *pg, *pgmid, *pw1T, *pw2T, *pfc1T;
    cudaGetSymbolAddress((void**)&ph,    d_h);
    cudaGetSymbolAddress((void**)&pg,    d_g);
    cudaGetSymbolAddress((void**)&pgmid, d_gmid);
    cudaGetSymbolAddress((void**)&pw1T,  d_w1T);
    cudaGetSymbolAddress((void**)&pw2T,  d_w2T);
    cudaGetSymbolAddress((void**)&pfc1T, d_fc1T);

    cudaFuncSetAttribute(fdft_kernel,
                         cudaFuncAttributeMaxDynamicSharedMemorySize, SMEM_FDFT);

    setup_kernel<<<18864, 256>>>(x_in, grid, fc0_w, fc0_b, g_w1, g_w2, fc1_w);

    for (int i = 0; i < 4; i++) {
        conv1x1_kernel<64, 128, 1><<<dim3(130, 16), 256>>>(
            ph, pw1T + i * 8192, g_b1 + i * 128, pgmid, nullptr);
        conv1x1_kernel<128, 64, 2><<<dim3(65, 16), 256>>>(
            pgmid, pw2T + i * 8192, g_b2 + i * 64, pg, ag);
        fdft_kernel<<<dim3(16, 16), 256, SMEM_FDFT>>>();
        reduce_kernel<<<1024, 256>>>();
        coefw_kernel<<<16, 256>>>(w_w, aw, i);
        modemix_kernel<<<dim3(16, 8), 512>>>(mix_re, mix_im, ldcy, w_b, aw, i);
        idft_kernel<<<dim3(65, 16), 256>>>((i < 3) ? 1 : 0);
    }

    conv1x1_kernel<64, 128, 1><<<dim3(128, 16), 256>>>(
        ph, pfc1T, fc1_b, pgmid, nullptr);
    fc2_kernel<<<dim3(128, 16), 128>>>(fc2_w, fc2_b, (float*)d_out);
}

// round 16
// speedup vs baseline: 1.4213x; 1.1241x over previous
#include <cuda_runtime.h>
#include <cuda_bf16.h>
#include <math.h>
#include <stdint.h>

#define XP    16386
#define XS    16640          // row stride (65*256)
#define NXV   16384
#define NB    16
#define NCHT  513            // 32-wide K chunks (513*32 = 16416 >= XP)

// ------------------- static device buffers -------------------
__device__ float d_h   [(size_t)NB * 64 * XS];
__device__ float d_g   [(size_t)NB * 64 * XS];
__device__ float d_gmid[(size_t)NB * 128 * XS];
__device__ __nv_bfloat16 d_bHi[(size_t)NCHT * 128 * 32];  // ftab^T hi [chunk][n][k]
__device__ __nv_bfloat16 d_bLo[(size_t)NCHT * 128 * 32];  // ftab^T lo
__device__ __nv_bfloat16 d_iHi[(size_t)XS * 128];         // itab^T hi [x][n]
__device__ __nv_bfloat16 d_iLo[(size_t)XS * 128];         // itab^T lo
__device__ __nv_bfloat16 d_cHi[(size_t)1024 * 200];       // coef hi [row][k(192)+pad]
__device__ __nv_bfloat16 d_cLo[(size_t)1024 * 200];
__device__ float d_part[(size_t)16 * 2048 * 128];
__device__ float d_fw  [2048 * 128];
__device__ float d_outm[1024 * 128];
__device__ float d_coefW[64 * 64];
__device__ float d_w1T [4 * 64 * 128];
__device__ float d_w2T [4 * 128 * 64];
__device__ float d_fc1T[64 * 128];

// ------------------- f32x2 packed helpers -------------------
__device__ __forceinline__ uint64_t pack2(float lo, float hi) {
    uint64_t r;
    asm("mov.b64 %0, {%1, %2};" : "=l"(r) : "f"(lo), "f"(hi));
    return r;
}
__device__ __forceinline__ void unpack2(uint64_t v, float& lo, float& hi) {
    asm("mov.b64 {%0, %1}, %2;" : "=f"(lo), "=f"(hi) : "l"(v));
}
#define FMA2(d, a, b) \
    asm("fma.rn.f32x2 %0, %1, %2, %0;" : "+l"(d) : "l"(a), "l"(b))

__device__ __forceinline__ uint32_t s2u(const void* p) {
    return (uint32_t)__cvta_generic_to_shared(p);
}
__device__ __forceinline__ void cp16(uint32_t s, const void* g) {
    asm volatile("cp.async.cg.shared.global [%0], [%1], 16;"
                 :: "r"(s), "l"(__cvta_generic_to_global(g)));
}
#define CP_COMMIT asm volatile("cp.async.commit_group;")
#define CP_WAIT(n) asm volatile("cp.async.wait_group %0;" :: "n"(n))

__device__ __forceinline__ float softplus_(float x) {
    return (x > 20.f) ? x : log1pf(expf(x));
}
__device__ __forceinline__ float gelu_(float v) {
    return 0.5f * v * (1.0f + erff(v * 0.70710678118654752f));
}

// ------------------- warp MMA helpers -------------------
__device__ __forceinline__ void ldsm_x4(uint32_t& r0, uint32_t& r1,
                                        uint32_t& r2, uint32_t& r3, uint32_t addr) {
    asm volatile("ldmatrix.sync.aligned.m8n8.x4.shared.b16 {%0,%1,%2,%3}, [%4];"
                 : "=r"(r0), "=r"(r1), "=r"(r2), "=r"(r3) : "r"(addr));
}
__device__ __forceinline__ void mma_bf16(float* c, const uint32_t* a,
                                         uint32_t b0, uint32_t b1) {
    asm volatile("mma.sync.aligned.m16n8k16.row.col.f32.bf16.bf16.f32 "
                 "{%0,%1,%2,%3}, {%4,%5,%6,%7}, {%8,%9}, {%0,%1,%2,%3};"
                 : "+f"(c[0]), "+f"(c[1]), "+f"(c[2]), "+f"(c[3])
                 : "r"(a[0]), "r"(a[1]), "r"(a[2]), "r"(a[3]), "r"(b0), "r"(b1));
}
__device__ __forceinline__ uint32_t bfpack(float a, float b) {
    __nv_bfloat16 h0 = __float2bfloat16(a);
    __nv_bfloat16 h1 = __float2bfloat16(b);
    return (uint32_t)__bfloat16_as_ushort(h0)
         | ((uint32_t)__bfloat16_as_ushort(h1) << 16);
}

// ------------------- mega setup kernel -------------------
// [0,1024) fc0 | [1024,2048) zero tail | [2048,2336) weight transposes
// [2336,10544) bf16 ftab^T hi/lo | [10544,18864) itab^T bf16 hi/lo
__global__ void __launch_bounds__(256) setup_kernel(
    const float* __restrict__ xin, const float* __restrict__ gin,
    const float* __restrict__ fc0_w, const float* __restrict__ fc0_b,
    const float* __restrict__ g_w1, const float* __restrict__ g_w2,
    const float* __restrict__ fc1_w)
{
    const int blk = blockIdx.x;
    const int tid = threadIdx.x;
    if (blk < 1024) {                             // ---- fc0 ----
        __shared__ float sw[64 * 32];
        __shared__ float sb[64];
        for (int l = tid; l < 64 * 31; l += 256) {
            int wo = l / 31, c = l - wo * 31;
            sw[wo * 32 + c] = fc0_w[l];
        }
        if (tid < 64) sb[tid] = fc0_b[tid];
        __syncthreads();
        int b = blk >> 6;
        int x = ((blk & 63) << 8) + tid;
        float rin[31];
        const float* xi = xin + ((size_t)b * NXV + x) * 30;
#pragma unroll
        for (int c = 0; c < 30; c++) rin[c] = __ldg(&xi[c]);
        rin[30] = __ldg(&gin[(size_t)b * NXV + x]);
        for (int wo = 0; wo < 64; wo++) {
            float acc = sb[wo];
#pragma unroll
            for (int c = 0; c < 31; c++) acc = fmaf(rin[c], sw[wo * 32 + c], acc);
            d_h[(size_t)(b * 64 + wo) * XS + x] = acc;
        }
    } else if (blk < 2048) {                      // ---- zero h tail ----
        int idx = (blk - 1024) * 256 + tid;
        int row = idx >> 8, col = NXV + (idx & 255);
        d_h[(size_t)row * XS + col] = 0.f;
    } else if (blk < 2336) {                      // ---- weight transposes ----
        int idx = (blk - 2048) * 256 + tid;
        if (idx < 32768) {
            int i = idx >> 13, r = idx & 8191, c = r >> 7, j = r & 127;
            d_w1T[idx] = g_w1[(i * 128 + j) * 64 + c];
        } else if (idx < 65536) {
            int t = idx - 32768;
            int i = t >> 13, r = t & 8191, j = r >> 6, o = r & 63;
            d_w2T[t] = g_w2[(i * 64 + o) * 128 + j];
        } else if (idx < 73728) {
            int t = idx - 65536;
            int c = t >> 7, j = t & 127;
            d_fc1T[t] = fc1_w[j * 64 + c];
        }
    } else if (blk < 10544) {                     // ---- bf16 ftab^T ----
        int idx = (blk - 2336) * 256 + tid;       // 513*4096
        int c = idx >> 12;
        int e = idx & 4095;
        int n = e >> 5, k = e & 31;
        int x = c * 32 + k;
        float v = 0.f;
        if (x < XP) {
            int u = (x * (n >> 1)) % XP;
            float s, co;
            sincospif(2.0f * (float)u / (float)XP, &s, &co);
            v = (n & 1) ? -s : co;
        }
        __nv_bfloat16 hi = __float2bfloat16(v);
        __nv_bfloat16 lo = __float2bfloat16(v - __bfloat162float(hi));
        d_bHi[idx] = hi;
        d_bLo[idx] = lo;
    } else {                                      // ---- itab^T bf16 [x][128] ----
        int idx = (blk - 10544) * 256 + tid;      // XS*128 = 2129920
        int x = idx >> 7, n = idx & 127, m = n >> 1;
        float v = 0.f;
        if (x < XP) {
            int u = (x * m) % XP;
            float s, c;
            sincospif(2.0f * (float)u / (float)XP, &s, &c);
            v = (n & 1) ? s : c;
        }
        __nv_bfloat16 hi = __float2bfloat16(v);
        __nv_bfloat16 lo = __float2bfloat16(v - __bfloat162float(hi));
        d_iHi[idx] = hi;
        d_iLo[idx] = lo;
    }
}

__global__ void coefw_kernel(const float* __restrict__ w_w,
                             const float* __restrict__ alpha_w, int blk) {
    int i = blockIdx.x * 256 + threadIdx.x;      // 4096
    d_coefW[i] = softplus_(__ldg(alpha_w)) * __ldg(&w_w[blk * 4096 + i]);
}

// convert coef (outm ++ coefW) to bf16 hi/lo, [row][200]
__global__ void coefcvt_kernel() {
    int idx = blockIdx.x * 256 + threadIdx.x;    // 1024*192 = 196608
    int row = idx / 192, k = idx - row * 192;
    float v = (k < 128) ? d_outm[(size_t)row * 128 + k]
                        : d_coefW[(row & 63) * 64 + (k - 128)];
    __nv_bfloat16 hi = __float2bfloat16(v);
    __nv_bfloat16 lo = __float2bfloat16(v - __bfloat162float(hi));
    d_cHi[(size_t)row * 200 + k] = hi;
    d_cLo[(size_t)row * 200 + k] = lo;
}

// ------------------- 1x1 conv (cp.async double-buffered, f32x2) -------------------
template<int CIN, int COUT, int ACT>
__global__ void __launch_bounds__(256, 2) conv1x1_kernel(
    const float* __restrict__ in,
    const float* __restrict__ wT,
    const float* __restrict__ bias,
    float* __restrict__ out,
    const float* __restrict__ alpha)
{
    constexpr int BP  = (COUT >= 128) ? 128 : 256;
    constexpr int TPp = BP / 32;
    constexpr int TOc = COUT / 8;
    constexpr int OP  = TOc / 2;
    constexpr int NTt = CIN / 16;
    constexpr int SIC = (16 * BP / 4) / 256;
    constexpr int SWC = (16 * COUT / 4) / 256;
    __shared__ float si [2][16][BP];
    __shared__ float swt[2][16][COUT];
    const int b   = blockIdx.y;
    const int p0  = blockIdx.x * BP;
    const int tid = threadIdx.x;
    const int po  = (tid & 31) * TPp;
    const int oo  = (tid >> 5) * TOc;

    const float* inb = in + (size_t)b * CIN * XS + p0;

    uint64_t acc[TPp][OP];
#pragma unroll
    for (int p = 0; p < TPp; p++)
#pragma unroll
        for (int j = 0; j < OP; j++) acc[p][j] = 0ull;

    {
#pragma unroll
        for (int l = 0; l < SIC; l++) {
            int c = l * 256 + tid;
            int k = c / (BP / 4), q = (c % (BP / 4)) * 4;
            cp16(s2u(&si[0][k][q]), inb + k * XS + q);
        }
#pragma unroll
        for (int l = 0; l < SWC; l++) {
            int c = l * 256 + tid;
            int k = c / (COUT / 4), q = (c % (COUT / 4)) * 4;
            cp16(s2u(&swt[0][k][q]), wT + k * COUT + q);
        }
        CP_COMMIT;
    }
#pragma unroll
    for (int t = 0; t < NTt; t++) {
        const int buf = t & 1;
        if (t + 1 < NTt) {
            const int c0 = (t + 1) * 16;
#pragma unroll
            for (int l = 0; l < SIC; l++) {
                int c = l * 256 + tid;
                int k = c / (BP / 4), q = (c % (BP / 4)) * 4;
                cp16(s2u(&si[buf ^ 1][k][q]), inb + (c0 + k) * XS + q);
            }
#pragma unroll
            for (int l = 0; l < SWC; l++) {
                int c = l * 256 + tid;
                int k = c / (COUT / 4), q = (c % (COUT / 4)) * 4;
                cp16(s2u(&swt[buf ^ 1][k][q]), wT + (c0 + k) * COUT + q);
            }
            CP_COMMIT;
            CP_WAIT(1);
        } else {
            CP_WAIT(0);
        }
        __syncthreads();
#pragma unroll
        for (int k = 0; k < 16; k++) {
            uint64_t pa[TPp];
#pragma unroll
            for (int u = 0; u < TPp / 4; u++) {
                float4 av = *(const float4*)&si[buf][k][po + 4 * u];
                pa[4*u+0] = pack2(av.x, av.x);
                pa[4*u+1] = pack2(av.y, av.y);
                pa[4*u+2] = pack2(av.z, av.z);
                pa[4*u+3] = pack2(av.w, av.w);
            }
#pragma unroll
            for (int j = 0; j < OP; j++) {
                uint64_t wv = *(const uint64_t*)&swt[buf][k][oo + 2 * j];
#pragma unroll
                for (int p = 0; p < TPp; p++) FMA2(acc[p][j], wv, pa[p]);
            }
        }
        __syncthreads();
    }

    float scv = 1.f;
    if (ACT == 2) scv = softplus_(__ldg(alpha));
#pragma unroll
    for (int j = 0; j < OP; j++) {
        int o0 = oo + 2 * j;
        float b0 = __ldg(&bias[o0]);
        float b1 = __ldg(&bias[o0 + 1]);
        float vlo[TPp], vhi[TPp];
#pragma unroll
        for (int p = 0; p < TPp; p++) {
            unpack2(acc[p][j], vlo[p], vhi[p]);
            vlo[p] += b0; vhi[p] += b1;
            if (ACT == 1) { vlo[p] = gelu_(vlo[p]); vhi[p] = gelu_(vhi[p]); }
            if (ACT == 2) { vlo[p] *= scv; vhi[p] *= scv; }
        }
        float* r0 = out + ((size_t)b * COUT + o0) * XS + p0 + po;
        float* r1 = r0 + XS;
#pragma unroll
        for (int q = 0; q < TPp / 4; q++) {
            *(float4*)&r0[4*q] = make_float4(vlo[4*q], vlo[4*q+1], vlo[4*q+2], vlo[4*q+3]);
            *(float4*)&r1[4*q] = make_float4(vhi[4*q], vhi[4*q+1], vhi[4*q+2], vhi[4*q+3]);
        }
    }
}

// ------------- forward DFT via warp-level split-bf16 mma.sync -------------
#define PAD 40
#define OFF_STAGE 0
#define OFF_AHI   16384
#define OFF_ALO   26624
#define OFF_B     36864
#define SMEM_FDFT 77824

__global__ void __launch_bounds__(256, 2) fdft_kernel() {
    extern __shared__ char smem[];
    const uint32_t sb = s2u(smem);
    const int tid = threadIdx.x;
    const int wid = tid >> 5, lane = tid & 31;
    const int rt = blockIdx.x;
    const int ks = blockIdx.y;
    const float* src = (rt < 8) ? d_h + (size_t)rt * 128 * XS
                                : d_g + (size_t)(rt - 8) * 128 * XS;
    const int ch0 = ks * 32;
    const int nch = (ks == 15) ? 33 : 32;

    const int wm = (wid >> 1) * 32;
    const int wn = (wid & 1) * 64;

    float acc[2][8][4];
#pragma unroll
    for (int mt = 0; mt < 2; mt++)
#pragma unroll
        for (int nt = 0; nt < 8; nt++)
#pragma unroll
            for (int j = 0; j < 4; j++) acc[mt][nt][j] = 0.f;

    {
        const int xb = ch0 * 32;
#pragma unroll
        for (int l = 0; l < 4; l++) {
            int c = l * 256 + tid;
            cp16(sb + OFF_STAGE + c * 16,
                 src + (size_t)(c >> 3) * XS + xb + (c & 7) * 4);
        }
#pragma unroll
        for (int l = 0; l < 2; l++) {
            int c = l * 256 + tid;
            int row = c >> 2, q = c & 3;
            cp16(sb + OFF_B + row * 80 + q * 16,
                 d_bHi + (size_t)ch0 * 4096 + row * 32 + q * 8);
            cp16(sb + OFF_B + 10240 + row * 80 + q * 16,
                 d_bLo + (size_t)ch0 * 4096 + row * 32 + q * 8);
        }
        CP_COMMIT;
        CP_WAIT(0);
        __syncthreads();
#pragma unroll
        for (int l = 0; l < 8; l++) {
            int idx = l * 256 + tid;
            int row = idx >> 4, kp = idx & 15;
            float2 v = *(const float2*)(smem + OFF_STAGE + (row * 32 + kp * 2) * 4);
            uint32_t hw = bfpack(v.x, v.y);
            __nv_bfloat16 h0 = __float2bfloat16(v.x);
            __nv_bfloat16 h1 = __float2bfloat16(v.y);
            uint32_t lw = bfpack(v.x - __bfloat162float(h0), v.y - __bfloat162float(h1));
            *(uint32_t*)(smem + OFF_AHI + row * 80 + kp * 4) = hw;
            *(uint32_t*)(smem + OFF_ALO + row * 80 + kp * 4) = lw;
        }
        __syncthreads();
    }

    for (int t = 0; t < nch; t++) {
        const int buf = t & 1;
        if (t + 1 < nch) {
            const int xb = (ch0 + t + 1) * 32;
#pragma unroll
            for (int l = 0; l < 4; l++) {
                int c = l * 256 + tid;
                cp16(sb + OFF_STAGE + c * 16,
                     src + (size_t)(c >> 3) * XS + xb + (c & 7) * 4);
            }
            const uint32_t bo = OFF_B + (buf ^ 1) * 20480;
#pragma unroll
            for (int l = 0; l < 2; l++) {
                int c = l * 256 + tid;
                int row = c >> 2, q = c & 3;
                cp16(sb + bo + row * 80 + q * 16,
                     d_bHi + (size_t)(ch0 + t + 1) * 4096 + row * 32 + q * 8);
                cp16(sb + bo + 10240 + row * 80 + q * 16,
                     d_bLo + (size_t)(ch0 + t + 1) * 4096 + row * 32 + q * 8);
            }
            CP_COMMIT;
        }
        const uint32_t bhB = sb + OFF_B + buf * 20480;
        const uint32_t blB = bhB + 10240;
#pragma unroll
        for (int k16 = 0; k16 < 2; k16++) {
            const int kc = k16 * 16 + ((lane >> 4) << 3);
            uint32_t ah[2][4], al[2][4];
#pragma unroll
            for (int mt = 0; mt < 2; mt++) {
                uint32_t aaddr = sb + OFF_AHI + (wm + mt * 16 + (lane & 15)) * 80 + kc * 2;
                ldsm_x4(ah[mt][0], ah[mt][1], ah[mt][2], ah[mt][3], aaddr);
                uint32_t laddr = sb + OFF_ALO + (wm + mt * 16 + (lane & 15)) * 80 + kc * 2;
                ldsm_x4(al[mt][0], al[mt][1], al[mt][2], al[mt][3], laddr);
            }
            const int brow = (lane & 7) + ((lane >> 4) << 3);
            const int bcol = k16 * 16 + (((lane >> 3) & 1) << 3);
#pragma unroll
            for (int p = 0; p < 4; p++) {
                uint32_t bh0, bh1, bh2, bh3, bl0, bl1, bl2, bl3;
                uint32_t off = (uint32_t)(wn + p * 16 + brow) * 80 + bcol * 2;
                ldsm_x4(bh0, bh1, bh2, bh3, bhB + off);
                ldsm_x4(bl0, bl1, bl2, bl3, blB + off);
#pragma unroll
                for (int mt = 0; mt < 2; mt++) {
                    mma_bf16(acc[mt][2 * p],     ah[mt], bh0, bh1);
                    mma_bf16(acc[mt][2 * p + 1], ah[mt], bh2, bh3);
                    mma_bf16(acc[mt][2 * p],     ah[mt], bl0, bl1);
                    mma_bf16(acc[mt][2 * p + 1], ah[mt], bl2, bl3);
                    mma_bf16(acc[mt][2 * p],     al[mt], bh0, bh1);
                    mma_bf16(acc[mt][2 * p + 1], al[mt], bh2, bh3);
                }
            }
        }
        if (t + 1 < nch) {
            CP_WAIT(0);
            __syncthreads();
#pragma unroll
            for (int l = 0; l < 8; l++) {
                int idx = l * 256 + tid;
                int row = idx >> 4, kp = idx & 15;
                float2 v = *(const float2*)(smem + OFF_STAGE + (row * 32 + kp * 2) * 4);
                uint32_t hw = bfpack(v.x, v.y);
                __nv_bfloat16 h0 = __float2bfloat16(v.x);
                __nv_bfloat16 h1 = __float2bfloat16(v.y);
                uint32_t lw = bfpack(v.x - __bfloat162float(h0), v.y - __bfloat162float(h1));
                *(uint32_t*)(smem + OFF_AHI + row * 80 + kp * 4) = hw;
                *(uint32_t*)(smem + OFF_ALO + row * 80 + kp * 4) = lw;
            }
            __syncthreads();
        }
    }

#pragma unroll
    for (int mt = 0; mt < 2; mt++)
#pragma unroll
        for (int nt = 0; nt < 8; nt++) {
            int row = rt * 128 + wm + mt * 16 + (lane >> 2);
            int col = wn + nt * 8 + (lane & 3) * 2;
            size_t base = ((size_t)ks * 2048 + row) * 128 + col;
            *(float2*)&d_part[base] = make_float2(acc[mt][nt][0], acc[mt][nt][1]);
            *(float2*)&d_part[base + 8 * 128] = make_float2(acc[mt][nt][2], acc[mt][nt][3]);
        }
}

__global__ void reduce_kernel() {
    int idx = blockIdx.x * 256 + threadIdx.x;   // 262144
    float s = 0.f;
#pragma unroll
    for (int k = 0; k < 16; k++) s += d_part[(size_t)k * 262144 + idx];
    d_fw[idx] = s;
}

// ------------------- mode mix + ETD coefficients (bias folded at m=0) -------------------
__global__ void __launch_bounds__(512) modemix_kernel(const float* __restrict__ mix_re,
                                                      const float* __restrict__ mix_im,
                                                      const float* __restrict__ log_decay,
                                                      const float* __restrict__ w_b,
                                                      const float* __restrict__ alpha_w,
                                                      int blk) {
    __shared__ float sg[64 * 128];
    const int b  = blockIdx.x;
    const int og = blockIdx.y;
    const int tid = threadIdx.x;
#pragma unroll
    for (int l = 0; l < 16; l++) {
        int idx = l * 512 + tid;
        sg[idx] = d_fw[(size_t)(1024 + b * 64) * 128 + idx];
    }
    __syncthreads();
    const int m = tid & 63, ol = tid >> 6;
    const int o = og * 8 + ol;
    const float* mr = mix_re + (size_t)blk * 262144 + o * 64 + m;
    const float* mi = mix_im + (size_t)blk * 262144 + o * 64 + m;
    float ar = 0.f, ai = 0.f;
#pragma unroll 4
    for (int i = 0; i < 64; i++) {
        float2 gh = *(const float2*)&sg[i * 128 + 2 * m];
        float r_ = __ldg(&mr[(size_t)i * 4096]);
        float i_ = __ldg(&mi[(size_t)i * 4096]);
        ar = fmaf(gh.x, r_, ar); ar = fmaf(-gh.y, i_, ar);
        ai = fmaf(gh.x, i_, ai); ai = fmaf( gh.y, r_, ai);
    }
    float ld = __ldg(&log_decay[((size_t)blk * 64 + o) * 64 + m]);
    float z  = -softplus_(ld);
    float ez = expf(z);
    float phi = (fabsf(z) < 1e-6f) ? (1.f + 0.5f * z + z * z * (1.f / 6.f))
                                   : (expm1f(z) / z);
    float gq = (float)m * (1.f / 63.f);
    float r2 = gq * gq + 1e-12f;
    float r8 = r2 * r2; r8 = r8 * r8;
    float pf = phi * expf(-2.f * r8);

    size_t vrow = ((size_t)b * 64 + o) * 128;
    float vr = d_fw[vrow + 2 * m], vi = d_fw[vrow + 2 * m + 1];
    float outr = fmaf(ez, vr, pf * ar);
    float outi = fmaf(ez, vi, pf * ai);
    const float inv = 1.0f / 16386.0f;
    float resr = (m == 0) ? outr * inv : 2.f * outr * inv;
    if (m == 0) resr += softplus_(__ldg(alpha_w)) * __ldg(&w_b[blk * 64 + o]);
    d_outm[vrow + 2 * m]     = resr;
    d_outm[vrow + 2 * m + 1] = (m == 0) ? 0.f : -2.f * outi * inv;
}

// ---- inverse DFT + fused w-skip + act via split-bf16 mma.sync ----
// D[64 rows][256 x] = coef[64][192] . T[192][x] per (b, x-block)
#define IA_PITCH 400   // A row bytes (200 bf16)
#define IB_PITCH 48    // B row bytes (24 bf16)
#define IOFF_AHI 0
#define IOFF_ALO 25600
#define IOFF_BHI 51200
#define IOFF_BLO 63488
#define IOFF_STG 75776
#define SMEM_IDFT 92160

__global__ void __launch_bounds__(256, 2) idft_kernel(int act) {
    extern __shared__ char smem[];
    const uint32_t sb = s2u(smem);
    const int tid = threadIdx.x;
    const int wid = tid >> 5, lane = tid & 31;
    const int x0 = blockIdx.x * 256;
    const int b  = blockIdx.y;
    float* hb = d_h + (size_t)b * 64 * XS;
    const int wm = (wid >> 2) * 32;
    const int wn = (wid & 3) * 64;

    float acc[2][8][4];
#pragma unroll
    for (int mt = 0; mt < 2; mt++)
#pragma unroll
        for (int nt = 0; nt < 8; nt++)
#pragma unroll
            for (int j = 0; j < 4; j++) acc[mt][nt][j] = 0.f;

    // load A coef tiles (hi+lo): 64 rows x 192 bf16 each
#pragma unroll
    for (int l = 0; l < 12; l++) {
        int c = l * 256 + tid;                 // 3072
        int tbl = (c >= 1536);
        int cc = tbl ? c - 1536 : c;
        int row = cc / 24, q = cc - row * 24;
        const __nv_bfloat16* srcp = (tbl ? d_cLo : d_cHi)
                                    + ((size_t)(b * 64 + row)) * 200 + q * 8;
        cp16(sb + (tbl ? IOFF_ALO : IOFF_AHI) + row * IA_PITCH + q * 16, srcp);
    }
    CP_COMMIT;

    for (int t = 0; t < 12; t++) {
        if (t < 8) {                           // itab^T tiles, straight cp.async
#pragma unroll
            for (int l = 0; l < 2; l++) {
                int c = l * 256 + tid;         // 512: x=c>>1, q=c&1
                int x = c >> 1, q = c & 1;
                cp16(sb + IOFF_BHI + x * IB_PITCH + q * 16,
                     d_iHi + ((size_t)(x0 + x)) * 128 + t * 16 + q * 8);
                cp16(sb + IOFF_BLO + x * IB_PITCH + q * 16,
                     d_iLo + ((size_t)(x0 + x)) * 128 + t * 16 + q * 8);
            }
            CP_COMMIT; CP_WAIT(0);
            __syncthreads();
        } else {                               // h skip tiles: stage + cvt-transpose
            const int r0 = (t - 8) * 16;
#pragma unroll
            for (int l = 0; l < 4; l++) {
                int c = l * 256 + tid;         // 1024: row=c>>6, q=c&63
                cp16(sb + IOFF_STG + c * 16,
                     hb + (size_t)(r0 + (c >> 6)) * XS + x0 + (c & 63) * 4);
            }
            CP_COMMIT; CP_WAIT(0);
            __syncthreads();
            const float* stg = (const float*)(smem + IOFF_STG);
#pragma unroll
            for (int kp = 0; kp < 8; kp++) {
                float v0 = stg[(2 * kp) * 256 + tid];
                float v1 = stg[(2 * kp + 1) * 256 + tid];
                uint32_t hw = bfpack(v0, v1);
                __nv_bfloat16 h0 = __float2bfloat16(v0);
                __nv_bfloat16 h1 = __float2bfloat16(v1);
                uint32_t lw = bfpack(v0 - __bfloat162float(h0), v1 - __bfloat162float(h1));
                *(uint32_t*)(smem + IOFF_BHI + tid * IB_PITCH + kp * 4) = hw;
                *(uint32_t*)(smem + IOFF_BLO + tid * IB_PITCH + kp * 4) = lw;
            }
            __syncthreads();
        }
        // compute this k-tile
        const int kc = t * 16 + ((lane >> 4) << 3);
        uint32_t ah[2][4], al[2][4];
#pragma unroll
        for (int mt = 0; mt < 2; mt++) {
            uint32_t r = (uint32_t)(wm + mt * 16 + (lane & 15));
            ldsm_x4(ah[mt][0], ah[mt][1], ah[mt][2], ah[mt][3],
                    sb + IOFF_AHI + r * IA_PITCH + kc * 2);
            ldsm_x4(al[mt][0], al[mt][1], al[mt][2], al[mt][3],
                    sb + IOFF_ALO + r * IA_PITCH + kc * 2);
        }
        const int brow = (lane & 7) + ((lane >> 4) << 3);
        const int bcolB = (((lane >> 3) & 1) << 3) * 2;
#pragma unroll
        for (int p = 0; p < 4; p++) {
            uint32_t off = (uint32_t)(wn + p * 16 + brow) * IB_PITCH + bcolB;
            uint32_t bh0, bh1, bh2, bh3, bl0, bl1, bl2, bl3;
            ldsm_x4(bh0, bh1, bh2, bh3, sb + IOFF_BHI + off);
            ldsm_x4(bl0, bl1, bl2, bl3, sb + IOFF_BLO + off);
#pragma unroll
            for (int mt = 0; mt < 2; mt++) {
                mma_bf16(acc[mt][2 * p],     ah[mt], bh0, bh1);
                mma_bf16(acc[mt][2 * p + 1], ah[mt], bh2, bh3);
                mma_bf16(acc[mt][2 * p],     ah[mt], bl0, bl1);
                mma_bf16(acc[mt][2 * p + 1], ah[mt], bl2, bl3);
                mma_bf16(acc[mt][2 * p],     al[mt], bh0, bh1);
                mma_bf16(acc[mt][2 * p + 1], al[mt], bh2, bh3);
            }
        }
        __syncthreads();
    }

    // epilogue: gelu + store
#pragma unroll
    for (int mt = 0; mt < 2; mt++)
#pragma unroll
        for (int nt = 0; nt < 8; nt++) {
            float c0 = acc[mt][nt][0], c1 = acc[mt][nt][1];
            float c2 = acc[mt][nt][2], c3 = acc[mt][nt][3];
            if (act) { c0 = gelu_(c0); c1 = gelu_(c1); c2 = gelu_(c2); c3 = gelu_(c3); }
            int row = wm + mt * 16 + (lane >> 2);
            int col = x0 + wn + nt * 8 + (lane & 3) * 2;
            *(float2*)&hb[(size_t)row * XS + col]       = make_float2(c0, c1);
            *(float2*)&hb[(size_t)(row + 8) * XS + col] = make_float2(c2, c3);
        }
}

// ------------------- fc2 -------------------
__global__ void __launch_bounds__(128) fc2_kernel(const float* __restrict__ w,
                                                  const float* __restrict__ bias,
                                                  float* __restrict__ out) {
    __shared__ float sw[3][128];
    int tid = threadIdx.x;
    for (int l = tid; l < 384; l += 128) sw[l >> 7][l & 127] = w[l];
    __syncthreads();
    int b = blockIdx.y;
    int x = blockIdx.x * 128 + tid;
    float a0 = __ldg(&bias[0]), a1 = __ldg(&bias[1]), a2 = __ldg(&bias[2]);
#pragma unroll 4
    for (int j = 0; j < 128; j++) {
        float v = d_gmid[((size_t)b * 128 + j) * XS + x];
        a0 = fmaf(v, sw[0][j], a0);
        a1 = fmaf(v, sw[1][j], a1);
        a2 = fmaf(v, sw[2][j], a2);
    }
    size_t o = ((size_t)b * NXV + x) * 3;
    out[o] = a0; out[o + 1] = a1; out[o + 2] = a2;
}

// ------------------- launch -------------------
extern "C" void kernel_launch(void* const* d_in, const int* in_sizes, int n_in,
                              void* d_out, int out_size) {
    const float* x_in   = (const float*)d_in[0];
    const float* grid   = (const float*)d_in[1];
    const float* fc0_w  = (const float*)d_in[2];
    const float* fc0_b  = (const float*)d_in[3];
    const float* fc1_w  = (const float*)d_in[4];
    const float* fc1_b  = (const float*)d_in[5];
    const float* fc2_w  = (const float*)d_in[6];
    const float* fc2_b  = (const float*)d_in[7];
    const float* g_w1   = (const float*)d_in[8];
    const float* g_b1   = (const float*)d_in[9];
    const float* g_w2   = (const float*)d_in[10];
    const float* g_b2   = (const float*)d_in[11];
    const float* w_w    = (const float*)d_in[12];
    const float* w_b    = (const float*)d_in[13];
    const float* ldcy   = (const float*)d_in[14];
    const float* mix_re = (const float*)d_in[15];
    const float* mix_im = (const float*)d_in[16];
    const float* aw     = (const float*)d_in[17];
    const float* ag     = (const float*)d_in[18];

    float *ph, *pg, *pgmid, *pw1T, *pw2T, *pfc1T;
    cudaGetSymbolAddress((void**)&ph,    d_h);
    cudaGetSymbolAddress((void**)&pg,    d_g);
    cudaGetSymbolAddress((void**)&pgmid, d_gmid);
    cudaGetSymbolAddress((void**)&pw1T,  d_w1T);
    cudaGetSymbolAddress((void**)&pw2T,  d_w2T);
    cudaGetSymbolAddress((void**)&pfc1T, d_fc1T);

    cudaFuncSetAttribute(fdft_kernel,
                         cudaFuncAttributeMaxDynamicSharedMemorySize, SMEM_FDFT);
    cudaFuncSetAttribute(idft_kernel,
                         cudaFuncAttributeMaxDynamicSharedMemorySize, SMEM_IDFT);

    setup_kernel<<<18864, 256>>>(x_in, grid, fc0_w, fc0_b, g_w1, g_w2, fc1_w);

    for (int i = 0; i < 4; i++) {
        conv1x1_kernel<64, 128, 1><<<dim3(130, 16), 256>>>(
            ph, pw1T + i * 8192, g_b1 + i * 128, pgmid, nullptr);
        conv1x1_kernel<128, 64, 2><<<dim3(65, 16), 256>>>(
            pgmid, pw2T + i * 8192, g_b2 + i * 64, pg, ag);
        fdft_kernel<<<dim3(16, 16), 256, SMEM_FDFT>>>();
        reduce_kernel<<<1024, 256>>>();
        coefw_kernel<<<16, 256>>>(w_w, aw, i);
        modemix_kernel<<<dim3(16, 8), 512>>>(mix_re, mix_im, ldcy, w_b, aw, i);
        coefcvt_kernel<<<768, 256>>>();
        idft_kernel<<<dim3(65, 16), 256, SMEM_IDFT>>>((i < 3) ? 1 : 0);
    }

    conv1x1_kernel<64, 128, 1><<<dim3(128, 16), 256>>>(
        ph, pfc1T, fc1_b, pgmid, nullptr);
    fc2_kernel<<<dim3(128, 16), 128>>>(fc2_w, fc2_b, (float*)d_out);
}

// round 17
// speedup vs baseline: 1.6051x; 1.1293x over previous
#include <cuda_runtime.h>
#include <cuda_bf16.h>
#include <math.h>
#include <stdint.h>

#define XP    16386
#define XS    16640          // row stride (65*256)
#define NXV   16384
#define NB    16
#define NCHT  513            // 32-wide K chunks (513*32 = 16416 >= XP)

// ------------------- static device buffers -------------------
__device__ float d_h   [(size_t)NB * 64 * XS];
__device__ float d_g   [(size_t)NB * 64 * XS];
__device__ float d_gmid[(size_t)NB * 128 * XS];
__device__ __nv_bfloat16 d_bHi[(size_t)NCHT * 128 * 32];  // ftab^T hi [chunk][n][k]
__device__ __nv_bfloat16 d_bLo[(size_t)NCHT * 128 * 32];  // ftab^T lo
__device__ __nv_bfloat16 d_iHi[(size_t)XS * 128];         // itab^T hi [x][n]
__device__ __nv_bfloat16 d_iLo[(size_t)XS * 128];         // itab^T lo
__device__ __nv_bfloat16 d_cHi[(size_t)1024 * 200];       // coef hi [row][k(192)+pad]
__device__ __nv_bfloat16 d_cLo[(size_t)1024 * 200];
__device__ __nv_bfloat16 d_w1H[4 * 128 * 64], d_w1L[4 * 128 * 64];
__device__ __nv_bfloat16 d_w2H[4 * 64 * 128], d_w2L[4 * 64 * 128];
__device__ __nv_bfloat16 d_f1H[128 * 64],     d_f1L[128 * 64];
__device__ float d_part[(size_t)16 * 2048 * 128];
__device__ float d_fw  [2048 * 128];
__device__ float d_outm[1024 * 128];
__device__ float d_coefW[64 * 64];

// ------------------- helpers -------------------
__device__ __forceinline__ uint32_t s2u(const void* p) {
    return (uint32_t)__cvta_generic_to_shared(p);
}
__device__ __forceinline__ void cp16(uint32_t s, const void* g) {
    asm volatile("cp.async.cg.shared.global [%0], [%1], 16;"
                 :: "r"(s), "l"(__cvta_generic_to_global(g)));
}
#define CP_COMMIT asm volatile("cp.async.commit_group;")
#define CP_WAIT(n) asm volatile("cp.async.wait_group %0;" :: "n"(n))

__device__ __forceinline__ float softplus_(float x) {
    return (x > 20.f) ? x : log1pf(expf(x));
}
__device__ __forceinline__ float gelu_(float v) {
    return 0.5f * v * (1.0f + erff(v * 0.70710678118654752f));
}

// ------------------- warp MMA helpers -------------------
__device__ __forceinline__ void ldsm_x4(uint32_t& r0, uint32_t& r1,
                                        uint32_t& r2, uint32_t& r3, uint32_t addr) {
    asm volatile("ldmatrix.sync.aligned.m8n8.x4.shared.b16 {%0,%1,%2,%3}, [%4];"
                 : "=r"(r0), "=r"(r1), "=r"(r2), "=r"(r3) : "r"(addr));
}
__device__ __forceinline__ void mma_bf16(float* c, const uint32_t* a,
                                         uint32_t b0, uint32_t b1) {
    asm volatile("mma.sync.aligned.m16n8k16.row.col.f32.bf16.bf16.f32 "
                 "{%0,%1,%2,%3}, {%4,%5,%6,%7}, {%8,%9}, {%0,%1,%2,%3};"
                 : "+f"(c[0]), "+f"(c[1]), "+f"(c[2]), "+f"(c[3])
                 : "r"(a[0]), "r"(a[1]), "r"(a[2]), "r"(a[3]), "r"(b0), "r"(b1));
}
__device__ __forceinline__ uint32_t bfpack(float a, float b) {
    __nv_bfloat16 h0 = __float2bfloat16(a);
    __nv_bfloat16 h1 = __float2bfloat16(b);
    return (uint32_t)__bfloat16_as_ushort(h0)
         | ((uint32_t)__bfloat16_as_ushort(h1) << 16);
}

// ------------------- mega setup kernel -------------------
// [0,1024) fc0 | [1024,2048) zero tail | [2048,2336) bf16 weight split
// [2336,10544) bf16 ftab^T hi/lo | [10544,18864) itab^T bf16 hi/lo
__global__ void __launch_bounds__(256) setup_kernel(
    const float* __restrict__ xin, const float* __restrict__ gin,
    const float* __restrict__ fc0_w, const float* __restrict__ fc0_b,
    const float* __restrict__ g_w1, const float* __restrict__ g_w2,
    const float* __restrict__ fc1_w)
{
    const int blk = blockIdx.x;
    const int tid = threadIdx.x;
    if (blk < 1024) {                             // ---- fc0 ----
        __shared__ float sw[64 * 32];
        __shared__ float sb[64];
        for (int l = tid; l < 64 * 31; l += 256) {
            int wo = l / 31, c = l - wo * 31;
            sw[wo * 32 + c] = fc0_w[l];
        }
        if (tid < 64) sb[tid] = fc0_b[tid];
        __syncthreads();
        int b = blk >> 6;
        int x = ((blk & 63) << 8) + tid;
        float rin[31];
        const float* xi = xin + ((size_t)b * NXV + x) * 30;
#pragma unroll
        for (int c = 0; c < 30; c++) rin[c] = __ldg(&xi[c]);
        rin[30] = __ldg(&gin[(size_t)b * NXV + x]);
        for (int wo = 0; wo < 64; wo++) {
            float acc = sb[wo];
#pragma unroll
            for (int c = 0; c < 31; c++) acc = fmaf(rin[c], sw[wo * 32 + c], acc);
            d_h[(size_t)(b * 64 + wo) * XS + x] = acc;
        }
    } else if (blk < 2048) {                      // ---- zero h tail ----
        int idx = (blk - 1024) * 256 + tid;
        int row = idx >> 8, col = NXV + (idx & 255);
        d_h[(size_t)row * XS + col] = 0.f;
    } else if (blk < 2336) {                      // ---- bf16 weight split ----
        int idx = (blk - 2048) * 256 + tid;       // 73728 total
        float v; __nv_bfloat16 *dh, *dl; int off;
        if (idx < 32768)      { v = g_w1[idx];          dh = d_w1H; dl = d_w1L; off = idx; }
        else if (idx < 65536) { v = g_w2[idx - 32768];  dh = d_w2H; dl = d_w2L; off = idx - 32768; }
        else if (idx < 73728) { v = fc1_w[idx - 65536]; dh = d_f1H; dl = d_f1L; off = idx - 65536; }
        else return;
        __nv_bfloat16 hi = __float2bfloat16(v);
        dh[off] = hi;
        dl[off] = __float2bfloat16(v - __bfloat162float(hi));
    } else if (blk < 10544) {                     // ---- bf16 ftab^T ----
        int idx = (blk - 2336) * 256 + tid;       // 513*4096
        int c = idx >> 12;
        int e = idx & 4095;
        int n = e >> 5, k = e & 31;
        int x = c * 32 + k;
        float v = 0.f;
        if (x < XP) {
            int u = (x * (n >> 1)) % XP;
            float s, co;
            sincospif(2.0f * (float)u / (float)XP, &s, &co);
            v = (n & 1) ? -s : co;
        }
        __nv_bfloat16 hi = __float2bfloat16(v);
        __nv_bfloat16 lo = __float2bfloat16(v - __bfloat162float(hi));
        d_bHi[idx] = hi;
        d_bLo[idx] = lo;
    } else {                                      // ---- itab^T bf16 [x][128] ----
        int idx = (blk - 10544) * 256 + tid;      // XS*128
        int x = idx >> 7, n = idx & 127, m = n >> 1;
        float v = 0.f;
        if (x < XP) {
            int u = (x * m) % XP;
            float s, c;
            sincospif(2.0f * (float)u / (float)XP, &s, &c);
            v = (n & 1) ? s : c;
        }
        __nv_bfloat16 hi = __float2bfloat16(v);
        __nv_bfloat16 lo = __float2bfloat16(v - __bfloat162float(hi));
        d_iHi[idx] = hi;
        d_iLo[idx] = lo;
    }
}

__global__ void coefw_kernel(const float* __restrict__ w_w,
                             const float* __restrict__ alpha_w, int blk) {
    int i = blockIdx.x * 256 + threadIdx.x;      // 4096
    d_coefW[i] = softplus_(__ldg(alpha_w)) * __ldg(&w_w[blk * 4096 + i]);
}

// convert coef (outm ++ coefW) to bf16 hi/lo, [row][200]
__global__ void coefcvt_kernel() {
    int idx = blockIdx.x * 256 + threadIdx.x;    // 196608
    int row = idx / 192, k = idx - row * 192;
    float v = (k < 128) ? d_outm[(size_t)row * 128 + k]
                        : d_coefW[(row & 63) * 64 + (k - 128)];
    __nv_bfloat16 hi = __float2bfloat16(v);
    d_cHi[(size_t)row * 200 + k] = hi;
    d_cLo[(size_t)row * 200 + k] = __float2bfloat16(v - __bfloat162float(hi));
}

// ---------- 1x1 conv via split-bf16 mma.sync ----------
// out[COUT][x] = ACT(W[COUT][CIN] . in[CIN][x] + bias)
template<int CIN, int COUT, int ACT>
__global__ void __launch_bounds__(256, 2) mconv_kernel(
    const float* __restrict__ in,
    const __nv_bfloat16* __restrict__ wHi,
    const __nv_bfloat16* __restrict__ wLo,
    const float* __restrict__ bias,
    float* __restrict__ out,
    const float* __restrict__ alpha)
{
    constexpr int N      = (COUT == 128) ? 128 : 256;
    constexpr int NWN    = N / 64;
    constexpr int APITCH = CIN * 2 + 16;
    constexpr int NK     = CIN / 16;
    constexpr int ASZ    = COUT * APITCH;
    constexpr int OFF_ALO_ = ASZ;
    constexpr int OFF_BHI_ = 2 * ASZ;
    constexpr int OFF_BLO_ = 2 * ASZ + N * 48;
    constexpr int OFF_STG_ = 2 * ASZ + 2 * N * 48;
    constexpr int STGB   = 16 * N * 4;         // one stage buffer bytes
    constexpr int CPR    = CIN * 2 / 16;       // A chunks per row
    constexpr int ACH    = COUT * CPR;         // chunks per A table (1024)
    constexpr int SC     = 16 * N / 4;         // stage chunks (512/1024)
    constexpr int NPW    = N * 8;              // B pair-writes

    extern __shared__ char smem[];
    const uint32_t sb = s2u(smem);
    const int tid = threadIdx.x;
    const int wid = tid >> 5, lane = tid & 31;
    const int x0 = blockIdx.x * N;
    const int b  = blockIdx.y;
    const int wm = (wid / NWN) * 32;
    const int wn = (wid % NWN) * 64;
    const float* inb = in + (size_t)b * CIN * XS + x0;

    float acc[2][8][4];
#pragma unroll
    for (int mt = 0; mt < 2; mt++)
#pragma unroll
        for (int nt = 0; nt < 8; nt++)
#pragma unroll
            for (int j = 0; j < 4; j++) acc[mt][nt][j] = 0.f;

    // prologue: A (hi+lo) + stage tile 0
#pragma unroll
    for (int l = 0; l < (2 * ACH) / 256; l++) {
        int c = l * 256 + tid;
        int tbl = c >= ACH; int cc = tbl ? c - ACH : c;
        int row = cc / CPR, q = cc % CPR;
        const __nv_bfloat16* srcp = (tbl ? wLo : wHi) + (size_t)row * CIN + q * 8;
        cp16(sb + (tbl ? OFF_ALO_ : 0) + row * APITCH + q * 16, srcp);
    }
#pragma unroll
    for (int l = 0; l < SC / 256; l++) {
        int c = l * 256 + tid;
        int kr = c / (N / 4), q = c % (N / 4);
        cp16(sb + OFF_STG_ + c * 16, inb + (size_t)kr * XS + q * 4);
    }
    CP_COMMIT; CP_WAIT(0);
    __syncthreads();
    // convert stage0 -> B
    {
        const float* stg = (const float*)(smem + OFF_STG_);
#pragma unroll
        for (int w = 0; w < NPW / 256; w++) {
            int c = w * 256 + tid;
            int x = c % N, kp = c / N;
            float v0 = stg[(2 * kp) * N + x];
            float v1 = stg[(2 * kp + 1) * N + x];
            uint32_t hw = bfpack(v0, v1);
            __nv_bfloat16 h0 = __float2bfloat16(v0);
            __nv_bfloat16 h1 = __float2bfloat16(v1);
            uint32_t lw = bfpack(v0 - __bfloat162float(h0), v1 - __bfloat162float(h1));
            *(uint32_t*)(smem + OFF_BHI_ + x * 48 + kp * 4) = hw;
            *(uint32_t*)(smem + OFF_BLO_ + x * 48 + kp * 4) = lw;
        }
    }
    __syncthreads();

    for (int t = 0; t < NK; t++) {
        if (t + 1 < NK) {
            const int so = OFF_STG_ + ((t + 1) & 1) * STGB;
#pragma unroll
            for (int l = 0; l < SC / 256; l++) {
                int c = l * 256 + tid;
                int kr = c / (N / 4), q = c % (N / 4);
                cp16(sb + so + c * 16,
                     inb + (size_t)((t + 1) * 16 + kr) * XS + q * 4);
            }
            CP_COMMIT;
        }
        // compute tile t
        const int kc = t * 16 + ((lane >> 4) << 3);
        uint32_t ah[2][4], al[2][4];
#pragma unroll
        for (int mt = 0; mt < 2; mt++) {
            uint32_t r = (uint32_t)(wm + mt * 16 + (lane & 15));
            ldsm_x4(ah[mt][0], ah[mt][1], ah[mt][2], ah[mt][3],
                    sb + r * APITCH + kc * 2);
            ldsm_x4(al[mt][0], al[mt][1], al[mt][2], al[mt][3],
                    sb + OFF_ALO_ + r * APITCH + kc * 2);
        }
        const int brow = (lane & 7) + ((lane >> 4) << 3);
        const int bcolB = (((lane >> 3) & 1) << 3) * 2;
#pragma unroll
        for (int p = 0; p < 4; p++) {
            uint32_t off = (uint32_t)(wn + p * 16 + brow) * 48 + bcolB;
            uint32_t bh0, bh1, bh2, bh3, bl0, bl1, bl2, bl3;
            ldsm_x4(bh0, bh1, bh2, bh3, sb + OFF_BHI_ + off);
            ldsm_x4(bl0, bl1, bl2, bl3, sb + OFF_BLO_ + off);
#pragma unroll
            for (int mt = 0; mt < 2; mt++) {
                mma_bf16(acc[mt][2 * p],     ah[mt], bh0, bh1);
                mma_bf16(acc[mt][2 * p + 1], ah[mt], bh2, bh3);
                mma_bf16(acc[mt][2 * p],     ah[mt], bl0, bl1);
                mma_bf16(acc[mt][2 * p + 1], ah[mt], bl2, bl3);
                mma_bf16(acc[mt][2 * p],     al[mt], bh0, bh1);
                mma_bf16(acc[mt][2 * p + 1], al[mt], bh2, bh3);
            }
        }
        if (t + 1 < NK) {
            CP_WAIT(0);
            __syncthreads();
            const float* stg = (const float*)(smem + OFF_STG_ + ((t + 1) & 1) * STGB);
#pragma unroll
            for (int w = 0; w < NPW / 256; w++) {
                int c = w * 256 + tid;
                int x = c % N, kp = c / N;
                float v0 = stg[(2 * kp) * N + x];
                float v1 = stg[(2 * kp + 1) * N + x];
                uint32_t hw = bfpack(v0, v1);
                __nv_bfloat16 h0 = __float2bfloat16(v0);
                __nv_bfloat16 h1 = __float2bfloat16(v1);
                uint32_t lw = bfpack(v0 - __bfloat162float(h0), v1 - __bfloat162float(h1));
                *(uint32_t*)(smem + OFF_BHI_ + x * 48 + kp * 4) = hw;
                *(uint32_t*)(smem + OFF_BLO_ + x * 48 + kp * 4) = lw;
            }
            __syncthreads();
        }
    }

    // epilogue
    float scv = 1.f;
    if (ACT == 2) scv = softplus_(__ldg(alpha));
#pragma unroll
    for (int mt = 0; mt < 2; mt++)
#pragma unroll
        for (int nt = 0; nt < 8; nt++) {
            int row = wm + mt * 16 + (lane >> 2);
            int col = x0 + wn + nt * 8 + (lane & 3) * 2;
            float b0 = __ldg(&bias[row]);
            float b1 = __ldg(&bias[row + 8]);
            float c0 = acc[mt][nt][0] + b0, c1 = acc[mt][nt][1] + b0;
            float c2 = acc[mt][nt][2] + b1, c3 = acc[mt][nt][3] + b1;
            if (ACT == 1) { c0 = gelu_(c0); c1 = gelu_(c1); c2 = gelu_(c2); c3 = gelu_(c3); }
            if (ACT == 2) { c0 *= scv; c1 *= scv; c2 *= scv; c3 *= scv; }
            *(float2*)&out[((size_t)b * COUT + row) * XS + col]     = make_float2(c0, c1);
            *(float2*)&out[((size_t)b * COUT + row + 8) * XS + col] = make_float2(c2, c3);
        }
}

// ------------- forward DFT via warp-level split-bf16 mma.sync -------------
#define OFF_STAGE 0
#define OFF_AHI   16384
#define OFF_ALO   26624
#define OFF_B     36864
#define SMEM_FDFT 77824

__global__ void __launch_bounds__(256, 2) fdft_kernel() {
    extern __shared__ char smem[];
    const uint32_t sb = s2u(smem);
    const int tid = threadIdx.x;
    const int wid = tid >> 5, lane = tid & 31;
    const int rt = blockIdx.x;
    const int ks = blockIdx.y;
    const float* src = (rt < 8) ? d_h + (size_t)rt * 128 * XS
                                : d_g + (size_t)(rt - 8) * 128 * XS;
    const int ch0 = ks * 32;
    const int nch = (ks == 15) ? 33 : 32;

    const int wm = (wid >> 1) * 32;
    const int wn = (wid & 1) * 64;

    float acc[2][8][4];
#pragma unroll
    for (int mt = 0; mt < 2; mt++)
#pragma unroll
        for (int nt = 0; nt < 8; nt++)
#pragma unroll
            for (int j = 0; j < 4; j++) acc[mt][nt][j] = 0.f;

    {
        const int xb = ch0 * 32;
#pragma unroll
        for (int l = 0; l < 4; l++) {
            int c = l * 256 + tid;
            cp16(sb + OFF_STAGE + c * 16,
                 src + (size_t)(c >> 3) * XS + xb + (c & 7) * 4);
        }
#pragma unroll
        for (int l = 0; l < 2; l++) {
            int c = l * 256 + tid;
            int row = c >> 2, q = c & 3;
            cp16(sb + OFF_B + row * 80 + q * 16,
                 d_bHi + (size_t)ch0 * 4096 + row * 32 + q * 8);
            cp16(sb + OFF_B + 10240 + row * 80 + q * 16,
                 d_bLo + (size_t)ch0 * 4096 + row * 32 + q * 8);
        }
        CP_COMMIT;
        CP_WAIT(0);
        __syncthreads();
#pragma unroll
        for (int l = 0; l < 8; l++) {
            int idx = l * 256 + tid;
            int row = idx >> 4, kp = idx & 15;
            float2 v = *(const float2*)(smem + OFF_STAGE + (row * 32 + kp * 2) * 4);
            uint32_t hw = bfpack(v.x, v.y);
            __nv_bfloat16 h0 = __float2bfloat16(v.x);
            __nv_bfloat16 h1 = __float2bfloat16(v.y);
            uint32_t lw = bfpack(v.x - __bfloat162float(h0), v.y - __bfloat162float(h1));
            *(uint32_t*)(smem + OFF_AHI + row * 80 + kp * 4) = hw;
            *(uint32_t*)(smem + OFF_ALO + row * 80 + kp * 4) = lw;
        }
        __syncthreads();
    }

    for (int t = 0; t < nch; t++) {
        const int buf = t & 1;
        if (t + 1 < nch) {
            const int xb = (ch0 + t + 1) * 32;
#pragma unroll
            for (int l = 0; l < 4; l++) {
                int c = l * 256 + tid;
                cp16(sb + OFF_STAGE + c * 16,
                     src + (size_t)(c >> 3) * XS + xb + (c & 7) * 4);
            }
            const uint32_t bo = OFF_B + (buf ^ 1) * 20480;
#pragma unroll
            for (int l = 0; l < 2; l++) {
                int c = l * 256 + tid;
                int row = c >> 2, q = c & 3;
                cp16(sb + bo + row * 80 + q * 16,
                     d_bHi + (size_t)(ch0 + t + 1) * 4096 + row * 32 + q * 8);
                cp16(sb + bo + 10240 + row * 80 + q * 16,
                     d_bLo + (size_t)(ch0 + t + 1) * 4096 + row * 32 + q * 8);
            }
            CP_COMMIT;
        }
        const uint32_t bhB = sb + OFF_B + buf * 20480;
        const uint32_t blB = bhB + 10240;
#pragma unroll
        for (int k16 = 0; k16 < 2; k16++) {
            const int kc = k16 * 16 + ((lane >> 4) << 3);
            uint32_t ah[2][4], al[2][4];
#pragma unroll
            for (int mt = 0; mt < 2; mt++) {
                uint32_t aaddr = sb + OFF_AHI + (wm + mt * 16 + (lane & 15)) * 80 + kc * 2;
                ldsm_x4(ah[mt][0], ah[mt][1], ah[mt][2], ah[mt][3], aaddr);
                uint32_t laddr = sb + OFF_ALO + (wm + mt * 16 + (lane & 15)) * 80 + kc * 2;
                ldsm_x4(al[mt][0], al[mt][1], al[mt][2], al[mt][3], laddr);
            }
            const int brow = (lane & 7) + ((lane >> 4) << 3);
            const int bcol = k16 * 16 + (((lane >> 3) & 1) << 3);
#pragma unroll
            for (int p = 0; p < 4; p++) {
                uint32_t bh0, bh1, bh2, bh3, bl0, bl1, bl2, bl3;
                uint32_t off = (uint32_t)(wn + p * 16 + brow) * 80 + bcol * 2;
                ldsm_x4(bh0, bh1, bh2, bh3, bhB + off);
                ldsm_x4(bl0, bl1, bl2, bl3, blB + off);
#pragma unroll
                for (int mt = 0; mt < 2; mt++) {
                    mma_bf16(acc[mt][2 * p],     ah[mt], bh0, bh1);
                    mma_bf16(acc[mt][2 * p + 1], ah[mt], bh2, bh3);
                    mma_bf16(acc[mt][2 * p],     ah[mt], bl0, bl1);
                    mma_bf16(acc[mt][2 * p + 1], ah[mt], bl2, bl3);
                    mma_bf16(acc[mt][2 * p],     al[mt], bh0, bh1);
                    mma_bf16(acc[mt][2 * p + 1], al[mt], bh2, bh3);
                }
            }
        }
        if (t + 1 < nch) {
            CP_WAIT(0);
            __syncthreads();
#pragma unroll
            for (int l = 0; l < 8; l++) {
                int idx = l * 256 + tid;
                int row = idx >> 4, kp = idx & 15;
                float2 v = *(const float2*)(smem + OFF_STAGE + (row * 32 + kp * 2) * 4);
                uint32_t hw = bfpack(v.x, v.y);
                __nv_bfloat16 h0 = __float2bfloat16(v.x);
                __nv_bfloat16 h1 = __float2bfloat16(v.y);
                uint32_t lw = bfpack(v.x - __bfloat162float(h0), v.y - __bfloat162float(h1));
                *(uint32_t*)(smem + OFF_AHI + row * 80 + kp * 4) = hw;
                *(uint32_t*)(smem + OFF_ALO + row * 80 + kp * 4) = lw;
            }
            __syncthreads();
        }
    }

#pragma unroll
    for (int mt = 0; mt < 2; mt++)
#pragma unroll
        for (int nt = 0; nt < 8; nt++) {
            int row = rt * 128 + wm + mt * 16 + (lane >> 2);
            int col = wn + nt * 8 + (lane & 3) * 2;
            size_t base = ((size_t)ks * 2048 + row) * 128 + col;
            *(float2*)&d_part[base] = make_float2(acc[mt][nt][0], acc[mt][nt][1]);
            *(float2*)&d_part[base + 8 * 128] = make_float2(acc[mt][nt][2], acc[mt][nt][3]);
        }
}

__global__ void reduce_kernel() {
    int idx = blockIdx.x * 256 + threadIdx.x;   // 262144
    float s = 0.f;
#pragma unroll
    for (int k = 0; k < 16; k++) s += d_part[(size_t)k * 262144 + idx];
    d_fw[idx] = s;
}

// ------------------- mode mix + ETD coefficients (bias folded at m=0) -------------------
__global__ void __launch_bounds__(512) modemix_kernel(const float* __restrict__ mix_re,
                                                      const float* __restrict__ mix_im,
                                                      const float* __restrict__ log_decay,
                                                      const float* __restrict__ w_b,
                                                      const float* __restrict__ alpha_w,
                                                      int blk) {
    __shared__ float sg[64 * 128];
    const int b  = blockIdx.x;
    const int og = blockIdx.y;
    const int tid = threadIdx.x;
#pragma unroll
    for (int l = 0; l < 16; l++) {
        int idx = l * 512 + tid;
        sg[idx] = d_fw[(size_t)(1024 + b * 64) * 128 + idx];
    }
    __syncthreads();
    const int m = tid & 63, ol = tid >> 6;
    const int o = og * 8 + ol;
    const float* mr = mix_re + (size_t)blk * 262144 + o * 64 + m;
    const float* mi = mix_im + (size_t)blk * 262144 + o * 64 + m;
    float ar = 0.f, ai = 0.f;
#pragma unroll 4
    for (int i = 0; i < 64; i++) {
        float2 gh = *(const float2*)&sg[i * 128 + 2 * m];
        float r_ = __ldg(&mr[(size_t)i * 4096]);
        float i_ = __ldg(&mi[(size_t)i * 4096]);
        ar = fmaf(gh.x, r_, ar); ar = fmaf(-gh.y, i_, ar);
        ai = fmaf(gh.x, i_, ai); ai = fmaf( gh.y, r_, ai);
    }
    float ld = __ldg(&log_decay[((size_t)blk * 64 + o) * 64 + m]);
    float z  = -softplus_(ld);
    float ez = expf(z);
    float phi = (fabsf(z) < 1e-6f) ? (1.f + 0.5f * z + z * z * (1.f / 6.f))
                                   : (expm1f(z) / z);
    float gq = (float)m * (1.f / 63.f);
    float r2 = gq * gq + 1e-12f;
    float r8 = r2 * r2; r8 = r8 * r8;
    float pf = phi * expf(-2.f * r8);

    size_t vrow = ((size_t)b * 64 + o) * 128;
    float vr = d_fw[vrow + 2 * m], vi = d_fw[vrow + 2 * m + 1];
    float outr = fmaf(ez, vr, pf * ar);
    float outi = fmaf(ez, vi, pf * ai);
    const float inv = 1.0f / 16386.0f;
    float resr = (m == 0) ? outr * inv : 2.f * outr * inv;
    if (m == 0) resr += softplus_(__ldg(alpha_w)) * __ldg(&w_b[blk * 64 + o]);
    d_outm[vrow + 2 * m]     = resr;
    d_outm[vrow + 2 * m + 1] = (m == 0) ? 0.f : -2.f * outi * inv;
}

// ---- inverse DFT + fused w-skip + act via split-bf16 mma.sync ----
#define IA_PITCH 400
#define IB_PITCH 48
#define IOFF_AHI 0
#define IOFF_ALO 25600
#define IOFF_BHI 51200
#define IOFF_BLO 63488
#define IOFF_STG 75776
#define SMEM_IDFT 92160

__global__ void __launch_bounds__(256, 2) idft_kernel(int act) {
    extern __shared__ char smem[];
    const uint32_t sb = s2u(smem);
    const int tid = threadIdx.x;
    const int wid = tid >> 5, lane = tid & 31;
    const int x0 = blockIdx.x * 256;
    const int b  = blockIdx.y;
    float* hb = d_h + (size_t)b * 64 * XS;
    const int wm = (wid >> 2) * 32;
    const int wn = (wid & 3) * 64;

    float acc[2][8][4];
#pragma unroll
    for (int mt = 0; mt < 2; mt++)
#pragma unroll
        for (int nt = 0; nt < 8; nt++)
#pragma unroll
            for (int j = 0; j < 4; j++) acc[mt][nt][j] = 0.f;

#pragma unroll
    for (int l = 0; l < 12; l++) {
        int c = l * 256 + tid;
        int tbl = (c >= 1536);
        int cc = tbl ? c - 1536 : c;
        int row = cc / 24, q = cc - row * 24;
        const __nv_bfloat16* srcp = (tbl ? d_cLo : d_cHi)
                                    + ((size_t)(b * 64 + row)) * 200 + q * 8;
        cp16(sb + (tbl ? IOFF_ALO : IOFF_AHI) + row * IA_PITCH + q * 16, srcp);
    }
    CP_COMMIT;

    for (int t = 0; t < 12; t++) {
        if (t < 8) {
#pragma unroll
            for (int l = 0; l < 2; l++) {
                int c = l * 256 + tid;
                int x = c >> 1, q = c & 1;
                cp16(sb + IOFF_BHI + x * IB_PITCH + q * 16,
                     d_iHi + ((size_t)(x0 + x)) * 128 + t * 16 + q * 8);
                cp16(sb + IOFF_BLO + x * IB_PITCH + q * 16,
                     d_iLo + ((size_t)(x0 + x)) * 128 + t * 16 + q * 8);
            }
            CP_COMMIT; CP_WAIT(0);
            __syncthreads();
        } else {
            const int r0 = (t - 8) * 16;
#pragma unroll
            for (int l = 0; l < 4; l++) {
                int c = l * 256 + tid;
                cp16(sb + IOFF_STG + c * 16,
                     hb + (size_t)(r0 + (c >> 6)) * XS + x0 + (c & 63) * 4);
            }
            CP_COMMIT; CP_WAIT(0);
            __syncthreads();
            const float* stg = (const float*)(smem + IOFF_STG);
#pragma unroll
            for (int kp = 0; kp < 8; kp++) {
                float v0 = stg[(2 * kp) * 256 + tid];
                float v1 = stg[(2 * kp + 1) * 256 + tid];
                uint32_t hw = bfpack(v0, v1);
                __nv_bfloat16 h0 = __float2bfloat16(v0);
                __nv_bfloat16 h1 = __float2bfloat16(v1);
                uint32_t lw = bfpack(v0 - __bfloat162float(h0), v1 - __bfloat162float(h1));
                *(uint32_t*)(smem + IOFF_BHI + tid * IB_PITCH + kp * 4) = hw;
                *(uint32_t*)(smem + IOFF_BLO + tid * IB_PITCH + kp * 4) = lw;
            }
            __syncthreads();
        }
        const int kc = t * 16 + ((lane >> 4) << 3);
        uint32_t ah[2][4], al[2][4];
#pragma unroll
        for (int mt = 0; mt < 2; mt++) {
            uint32_t r = (uint32_t)(wm + mt * 16 + (lane & 15));
            ldsm_x4(ah[mt][0], ah[mt][1], ah[mt][2], ah[mt][3],
                    sb + IOFF_AHI + r * IA_PITCH + kc * 2);
            ldsm_x4(al[mt][0], al[mt][1], al[mt][2], al[mt][3],
                    sb + IOFF_ALO + r * IA_PITCH + kc * 2);
        }
        const int brow = (lane & 7) + ((lane >> 4) << 3);
        const int bcolB = (((lane >> 3) & 1) << 3) * 2;
#pragma unroll
        for (int p = 0; p < 4; p++) {
            uint32_t off = (uint32_t)(wn + p * 16 + brow) * IB_PITCH + bcolB;
            uint32_t bh0, bh1, bh2, bh3, bl0, bl1, bl2, bl3;
            ldsm_x4(bh0, bh1, bh2, bh3, sb + IOFF_BHI + off);
            ldsm_x4(bl0, bl1, bl2, bl3, sb + IOFF_BLO + off);
#pragma unroll
            for (int mt = 0; mt < 2; mt++) {
                mma_bf16(acc[mt][2 * p],     ah[mt], bh0, bh1);
                mma_bf16(acc[mt][2 * p + 1], ah[mt], bh2, bh3);
                mma_bf16(acc[mt][2 * p],     ah[mt], bl0, bl1);
                mma_bf16(acc[mt][2 * p + 1], ah[mt], bl2, bl3);
                mma_bf16(acc[mt][2 * p],     al[mt], bh0, bh1);
                mma_bf16(acc[mt][2 * p + 1], al[mt], bh2, bh3);
            }
        }
        __syncthreads();
    }

#pragma unroll
    for (int mt = 0; mt < 2; mt++)
#pragma unroll
        for (int nt = 0; nt < 8; nt++) {
            float c0 = acc[mt][nt][0], c1 = acc[mt][nt][1];
            float c2 = acc[mt][nt][2], c3 = acc[mt][nt][3];
            if (act) { c0 = gelu_(c0); c1 = gelu_(c1); c2 = gelu_(c2); c3 = gelu_(c3); }
            int row = wm + mt * 16 + (lane >> 2);
            int col = x0 + wn + nt * 8 + (lane & 3) * 2;
            *(float2*)&hb[(size_t)row * XS + col]       = make_float2(c0, c1);
            *(float2*)&hb[(size_t)(row + 8) * XS + col] = make_float2(c2, c3);
        }
}

// ------------------- fc2 -------------------
__global__ void __launch_bounds__(128) fc2_kernel(const float* __restrict__ w,
                                                  const float* __restrict__ bias,
                                                  float* __restrict__ out) {
    __shared__ float sw[3][128];
    int tid = threadIdx.x;
    for (int l = tid; l < 384; l += 128) sw[l >> 7][l & 127] = w[l];
    __syncthreads();
    int b = blockIdx.y;
    int x = blockIdx.x * 128 + tid;
    float a0 = __ldg(&bias[0]), a1 = __ldg(&bias[1]), a2 = __ldg(&bias[2]);
#pragma unroll 4
    for (int j = 0; j < 128; j++) {
        float v = d_gmid[((size_t)b * 128 + j) * XS + x];
        a0 = fmaf(v, sw[0][j], a0);
        a1 = fmaf(v, sw[1][j], a1);
        a2 = fmaf(v, sw[2][j], a2);
    }
    size_t o = ((size_t)b * NXV + x) * 3;
    out[o] = a0; out[o + 1] = a1; out[o + 2] = a2;
}

// ------------------- launch -------------------
extern "C" void kernel_launch(void* const* d_in, const int* in_sizes, int n_in,
                              void* d_out, int out_size) {
    const float* x_in   = (const float*)d_in[0];
    const float* grid   = (const float*)d_in[1];
    const float* fc0_w  = (const float*)d_in[2];
    const float* fc0_b  = (const float*)d_in[3];
    const float* fc1_w  = (const float*)d_in[4];
    const float* fc1_b  = (const float*)d_in[5];
    const float* fc2_w  = (const float*)d_in[6];
    const float* fc2_b  = (const float*)d_in[7];
    const float* g_w1   = (const float*)d_in[8];
    const float* g_b1   = (const float*)d_in[9];
    const float* g_w2   = (const float*)d_in[10];
    const float* g_b2   = (const float*)d_in[11];
    const float* w_w    = (const float*)d_in[12];
    const float* w_b    = (const float*)d_in[13];
    const float* ldcy   = (const float*)d_in[14];
    const float* mix_re = (const float*)d_in[15];
    const float* mix_im = (const float*)d_in[16];
    const float* aw     = (const float*)d_in[17];
    const float* ag     = (const float*)d_in[18];

    float *ph, *pg, *pgmid;
    __nv_bfloat16 *pw1H, *pw1L, *pw2H, *pw2L, *pf1H, *pf1L;
    cudaGetSymbolAddress((void**)&ph,    d_h);
    cudaGetSymbolAddress((void**)&pg,    d_g);
    cudaGetSymbolAddress((void**)&pgmid, d_gmid);
    cudaGetSymbolAddress((void**)&pw1H,  d_w1H);
    cudaGetSymbolAddress((void**)&pw1L,  d_w1L);
    cudaGetSymbolAddress((void**)&pw2H,  d_w2H);
    cudaGetSymbolAddress((void**)&pw2L,  d_w2L);
    cudaGetSymbolAddress((void**)&pf1H,  d_f1H);
    cudaGetSymbolAddress((void**)&pf1L,  d_f1L);

    cudaFuncSetAttribute(fdft_kernel,
                         cudaFuncAttributeMaxDynamicSharedMemorySize, SMEM_FDFT);
    cudaFuncSetAttribute(idft_kernel,
                         cudaFuncAttributeMaxDynamicSharedMemorySize, SMEM_IDFT);
    cudaFuncSetAttribute(mconv_kernel<64, 128, 1>,
                         cudaFuncAttributeMaxDynamicSharedMemorySize, 65536);
    cudaFuncSetAttribute(mconv_kernel<128, 64, 2>,
                         cudaFuncAttributeMaxDynamicSharedMemorySize, 92160);

    setup_kernel<<<18864, 256>>>(x_in, grid, fc0_w, fc0_b, g_w1, g_w2, fc1_w);

    for (int i = 0; i < 4; i++) {
        mconv_kernel<64, 128, 1><<<dim3(130, 16), 256, 65536>>>(
            ph, pw1H + i * 8192, pw1L + i * 8192, g_b1 + i * 128, pgmid, nullptr);
        mconv_kernel<128, 64, 2><<<dim3(65, 16), 256, 92160>>>(
            pgmid, pw2H + i * 8192, pw2L + i * 8192, g_b2 + i * 64, pg, ag);
        fdft_kernel<<<dim3(16, 16), 256, SMEM_FDFT>>>();
        reduce_kernel<<<1024, 256>>>();
        coefw_kernel<<<16, 256>>>(w_w, aw, i);
        modemix_kernel<<<dim3(16, 8), 512>>>(mix_re, mix_im, ldcy, w_b, aw, i);
        coefcvt_kernel<<<768, 256>>>();
        idft_kernel<<<dim3(65, 16), 256, SMEM_IDFT>>>((i < 3) ? 1 : 0);
    }

    mconv_kernel<64, 128, 1><<<dim3(128, 16), 256, 65536>>>(
        ph, pf1H, pf1L, fc1_b, pgmid, nullptr);
    fc2_kernel<<<dim3(128, 16), 128>>>(fc2_w, fc2_b, (float*)d_out);
}